// round 12
// baseline (speedup 1.0000x reference)
#include <cuda_runtime.h>
#include <cuda_fp16.h>
#include <cstdint>
#include <math.h>

#define NBATCH 4
#define TSEQ   2048
#define DMODEL 1024
#define NHEADS 16
#define HDIM   64
#define MROWS  (NBATCH * TSEQ)   // 8192
#define KDIM   DMODEL            // 1024
#define D3     (3 * DMODEL)

// ---------------- scratch (static device globals; no runtime alloc) --------
__device__ __align__(1024) __half g_xh[(size_t)MROWS * DMODEL];        // 16 MB
__device__ __align__(1024) __half g_qkvh[(size_t)MROWS * D3];          // 50 MB
__device__ __align__(1024) __half g_yh[(size_t)MROWS * DMODEL];        // 16 MB
__device__ __align__(1024) __half g_wqkvh[(size_t)KDIM * D3];          // 6 MB
__device__ __align__(1024) __half g_woh[(size_t)KDIM * DMODEL];        // 2 MB

// ---------------- helpers ---------------------------------------------------
#define CP_ASYNC16(dst, src) \
    asm volatile("cp.async.cg.shared.global [%0], [%1], 16;" \
                 :: "r"(dst), "l"(src) : "memory")
#define CP_COMMIT() asm volatile("cp.async.commit_group;" ::: "memory")
#define CP_WAIT1()  asm volatile("cp.async.wait_group 1;" ::: "memory")
#define CP_WAIT0()  asm volatile("cp.async.wait_group 0;" ::: "memory")

__device__ __forceinline__ uint32_t smem_u32(const void* p) {
    uint32_t a;
    asm("{ .reg .u64 t; cvta.to.shared.u64 t, %1; cvt.u32.u64 %0, t; }"
        : "=r"(a) : "l"(p));
    return a;
}

#define MMA_F16(d, a, b) \
    asm volatile("mma.sync.aligned.m16n8k16.row.col.f32.f16.f16.f32 " \
        "{%0,%1,%2,%3}, {%4,%5,%6,%7}, {%8,%9}, {%0,%1,%2,%3};" \
        : "+f"((d)[0]), "+f"((d)[1]), "+f"((d)[2]), "+f"((d)[3]) \
        : "r"((a)[0]), "r"((a)[1]), "r"((a)[2]), "r"((a)[3]), \
          "r"((b)[0]), "r"((b)[1]))

#define LDSM_X4(r0, r1, r2, r3, addr) \
    asm volatile("ldmatrix.sync.aligned.m8n8.x4.shared.b16 {%0,%1,%2,%3}, [%4];" \
        : "=r"(r0), "=r"(r1), "=r"(r2), "=r"(r3) : "r"(addr))
#define LDSM_X4_T(r0, r1, r2, r3, addr) \
    asm volatile("ldmatrix.sync.aligned.m8n8.x4.trans.shared.b16 {%0,%1,%2,%3}, [%4];" \
        : "=r"(r0), "=r"(r1), "=r"(r2), "=r"(r3) : "r"(addr))

__device__ __forceinline__ void store_pair(float* p, float a, float b) {
    *(float2*)p = make_float2(a, b);
}
__device__ __forceinline__ void store_pair(__half* p, float a, float b) {
    *(__half2*)p = __floats2half2_rn(a, b);
}

__device__ __forceinline__ float h2sum(__half2 v) {
    return __half2float(__hadd(__low2half(v), __high2half(v)));
}

// ---------------- prep: fused fp32 -> fp16 convert (3 segments) ------------
__global__ void f2h3_kernel(const float* __restrict__ in0, __half* __restrict__ out0, int n0,
                            const float* __restrict__ in1, __half* __restrict__ out1, int n1,
                            const float* __restrict__ in2, __half* __restrict__ out2, int n2)
{
    const int ntot = n0 + n1 + n2;
    for (int i = blockIdx.x * blockDim.x + threadIdx.x; i < ntot;
         i += gridDim.x * blockDim.x) {
        const float* in; __half* out; int j = i;
        if (j < n0)            { in = in0; out = out0; }
        else if ((j -= n0) < n1) { in = in1; out = out1; }
        else                   { j -= n1; in = in2; out = out2; }
        float4 v = *(const float4*)(in + (size_t)j * 4);
        __half2 h0 = __floats2half2_rn(v.x, v.y);
        __half2 h1 = __floats2half2_rn(v.z, v.w);
        *(uint2*)(out + (size_t)j * 4) =
            make_uint2(*(uint32_t*)&h0, *(uint32_t*)&h1);
    }
}

// ---------------- fp16 mma GEMM (unchanged from R9/R10) --------------------
#define GBK 64
#define GAP 72
#define GBP 136
#define ATILE_H (128 * GAP)
#define BTILE_H (GBK * GBP)
#define STAGE_H (ATILE_H + BTILE_H)
#define HSMEM_BYTES (3 * STAGE_H * 2)        // 107520 B
#define GCHUNKS (KDIM / GBK)                 // 16

template <typename OutT>
__global__ __launch_bounds__(256, 2) void gemm_h_kernel(
    const __half* __restrict__ A, const __half* __restrict__ W,
    const float* __restrict__ bias, OutT* __restrict__ C, int N)
{
    extern __shared__ __half hsm[];
    const int tid = threadIdx.x;
    const int wid = tid >> 5;
    const int lane = tid & 31;
    const int gid = lane >> 2;
    const int tig = lane & 3;

    const size_t row0 = (size_t)blockIdx.y * 128;
    const size_t col0 = (size_t)blockIdx.x * 128;
    const int wm0 = (wid & 3) * 32;
    const int wn0 = (wid >> 2) * 64;

    const __half* Ab = A + row0 * KDIM;

    float acc[2][8][4];
#pragma unroll
    for (int mt = 0; mt < 2; mt++)
#pragma unroll
        for (int nt = 0; nt < 8; nt++)
#pragma unroll
            for (int j = 0; j < 4; j++) acc[mt][nt][j] = 0.f;

    const uint32_t sbase = smem_u32(hsm);

    const int aRow = lane & 15, aColSel = (lane >> 4) * 8;
    const int tRow = (lane & 7) + (((lane >> 3) & 1) << 3);
    const int tColSel = (lane >> 4) * 8;

    auto load_stage = [&](int s, int chunk) {
        const int kof = chunk * GBK;
        uint32_t aS = sbase + (uint32_t)(s * STAGE_H) * 2u;
        uint32_t bS = aS + (uint32_t)ATILE_H * 2u;
#pragma unroll
        for (int i = 0; i < 4; i++) {
            int idx = tid + i * 256;
            int r = idx >> 3, ch = idx & 7;
            CP_ASYNC16(aS + (uint32_t)(r * GAP + ch * 8) * 2u,
                       Ab + (size_t)r * KDIM + kof + ch * 8);
        }
#pragma unroll
        for (int i = 0; i < 4; i++) {
            int idx = tid + i * 256;
            int r = idx >> 4, ch = idx & 15;
            CP_ASYNC16(bS + (uint32_t)(r * GBP + ch * 8) * 2u,
                       W + (size_t)(kof + r) * N + col0 + ch * 8);
        }
    };

    load_stage(0, 0); CP_COMMIT();
    load_stage(1, 1); CP_COMMIT();

    for (int c = 0; c < GCHUNKS; c++) {
        CP_WAIT1();
        __syncthreads();
        if (c + 2 < GCHUNKS) load_stage((c + 2) % 3, c + 2);
        CP_COMMIT();

        const uint32_t aS = sbase + (uint32_t)((c % 3) * STAGE_H) * 2u;
        const uint32_t bS = aS + (uint32_t)ATILE_H * 2u;
#pragma unroll
        for (int kk = 0; kk < 4; kk++) {
            const int kb = kk * 16;
            uint32_t a[2][4];
#pragma unroll
            for (int mt = 0; mt < 2; mt++) {
                uint32_t ad = aS + (uint32_t)((wm0 + mt * 16 + aRow) * GAP + kb + aColSel) * 2u;
                LDSM_X4(a[mt][0], a[mt][1], a[mt][2], a[mt][3], ad);
            }
            uint32_t b[8][2];
#pragma unroll
            for (int np = 0; np < 4; np++) {
                uint32_t bd = bS + (uint32_t)((kb + tRow) * GBP + wn0 + np * 16 + tColSel) * 2u;
                LDSM_X4_T(b[2 * np][0], b[2 * np][1], b[2 * np + 1][0], b[2 * np + 1][1], bd);
            }
#pragma unroll
            for (int mt = 0; mt < 2; mt++)
#pragma unroll
                for (int nt = 0; nt < 8; nt++)
                    MMA_F16(acc[mt][nt], a[mt], b[nt]);
        }
    }

#pragma unroll
    for (int mt = 0; mt < 2; mt++) {
        size_t r = row0 + wm0 + mt * 16 + gid;
#pragma unroll
        for (int nt = 0; nt < 8; nt++) {
            size_t col = col0 + wn0 + nt * 8 + tig * 2;
            float2 bb = *(const float2*)(bias + col);
            store_pair(C + r * N + col, acc[mt][nt][0] + bb.x, acc[mt][nt][1] + bb.y);
            store_pair(C + (r + 8) * N + col, acc[mt][nt][2] + bb.x, acc[mt][nt][3] + bb.y);
        }
    }
}

// ---------------- fp16 flash attention: 32 q-rows per warp -----------------
// CTA covers 256 q-rows (8 warps x 32 rows); 64-key tiles; K/V fragments
// reused across 2 m-frags per warp AND amortized over 2x q-work per load
// -> ~2x less SMEM crossbar traffic per unit work (was the binding pipe).
// log2-domain softmax with ex2.approx.f16x2 (R11). cp.async K/V prefetch.
#define ABM 256
#define APH 72
#define KVT_H (64 * APH)
#define ATT_SMEM_BYTES ((4 * KVT_H + ABM * APH) * 2)   // 73728 B

__global__ __launch_bounds__(256, 1) void attn_h_kernel(
    const __half* __restrict__ qkv, __half* __restrict__ y)
{
    extern __shared__ __half dsm[];
    __half* Ps = dsm + 4 * KVT_H;            // [ABM][APH]

    const int qb  = gridDim.x - 1 - blockIdx.x;    // big tiles first
    const int bh  = blockIdx.y;
    const int b   = bh >> 4;
    const int h   = bh & 15;
    const int tid = threadIdx.x;
    const int wid = tid >> 5;
    const int lane = tid & 31;
    const int gid = lane >> 2;
    const int tig = lane & 3;
    const int wrow = wid * 32;               // warp's first q row in tile
    const int q0 = qb * ABM;

    const __half* base = qkv + (size_t)b * TSEQ * D3;
    const uint32_t smS = smem_u32(dsm);
    const uint32_t psS = smem_u32(Ps);

    const int aRow = lane & 15, aColSel = (lane >> 4) * 8;
    const int bRow = (lane & 7) + ((lane >> 4) << 3);
    const int bColSel = ((lane >> 3) & 1) * 8;
    const int vRow = (lane & 7) + (((lane >> 3) & 1) << 3);
    const int vColSel = (lane >> 4) * 8;

    const int ntiles = (qb + 1) * (ABM / 64);      // 64-key tiles

    auto load_kv = [&](int t, int s) {
        const int k0 = t * 64;
        uint32_t kS = smS + (uint32_t)(s * 2 * KVT_H) * 2u;
        uint32_t vS = kS + (uint32_t)KVT_H * 2u;
        const __half* kb_ = base + (size_t)k0 * D3 + DMODEL + h * HDIM;
#pragma unroll
        for (int i = 0; i < 2; i++) {
            int idx = tid + i * 256;
            int r = idx >> 3, ch = idx & 7;
            uint32_t off = (uint32_t)(r * APH + ch * 8) * 2u;
            const __half* src = kb_ + (size_t)r * D3 + ch * 8;
            CP_ASYNC16(kS + off, src);
            CP_ASYNC16(vS + off, src + DMODEL);
        }
    };

    // prologue: kick tile-0 K/V load; stage Q (scaled, log2 domain) meanwhile
    load_kv(0, 0); CP_COMMIT();

    {
        const __half2 s = __float2half2_rn(0.125f * 1.44269504089f);
#pragma unroll
        for (int i = 0; i < 8; i++) {              // ABM*64/8 = 2048 uint4
            int idx = tid + i * 256;
            int r = idx >> 3, c8 = (idx & 7) << 3;
            uint4 v = *(const uint4*)(base + (size_t)(q0 + r) * D3 + h * HDIM + c8);
            __half2* h2 = reinterpret_cast<__half2*>(&v);
            h2[0] = __hmul2(h2[0], s); h2[1] = __hmul2(h2[1], s);
            h2[2] = __hmul2(h2[2], s); h2[3] = __hmul2(h2[3], s);
            *(uint4*)&Ps[r * APH + c8] = v;
        }
    }
    __syncthreads();

    uint32_t qf[4][2][4];
#pragma unroll
    for (int kk = 0; kk < 4; kk++)
#pragma unroll
        for (int mt = 0; mt < 2; mt++) {
            uint32_t ad = psS +
                (uint32_t)((wrow + mt * 16 + aRow) * APH + kk * 16 + aColSel) * 2u;
            LDSM_X4(qf[kk][mt][0], qf[kk][mt][1], qf[kk][mt][2], qf[kk][mt][3], ad);
        }

    // this thread's 4 global q rows: [mt][j] -> q0+wrow+mt*16+gid (+8 for j=1)
    int rg[2][2];
    rg[0][0] = q0 + wrow + gid;      rg[0][1] = rg[0][0] + 8;
    rg[1][0] = rg[0][0] + 16;        rg[1][1] = rg[0][0] + 24;
    const int rlast = q0 + wrow + 31;

    float m[2][2] = {{-1e30f, -1e30f}, {-1e30f, -1e30f}};
    float l[2][2] = {{0.f, 0.f}, {0.f, 0.f}};
    float oacc[2][8][4];
#pragma unroll
    for (int mt = 0; mt < 2; mt++)
#pragma unroll
        for (int nt = 0; nt < 8; nt++)
#pragma unroll
            for (int j = 0; j < 4; j++) oacc[mt][nt][j] = 0.f;

    for (int t = 0; t < ntiles; t++) {
        const int k0 = t * 64;
        CP_WAIT0();
        __syncthreads();
        if (t + 1 < ntiles) { load_kv(t + 1, (t + 1) & 1); CP_COMMIT(); }

        if (k0 > rlast) continue;                  // warp fully masked

        const uint32_t kS = smS + (uint32_t)((t & 1) * 2 * KVT_H) * 2u;
        const uint32_t vS = kS + (uint32_t)KVT_H * 2u;

        // ---- S = Q @ K^T (log2 domain), K frags reused across mt ----
        float sacc[2][8][4];
#pragma unroll
        for (int mt = 0; mt < 2; mt++)
#pragma unroll
            for (int nt = 0; nt < 8; nt++)
#pragma unroll
                for (int j = 0; j < 4; j++) sacc[mt][nt][j] = 0.f;
#pragma unroll
        for (int kk = 0; kk < 4; kk++) {
            const int kb = kk * 16;
            uint32_t bf[8][2];
#pragma unroll
            for (int np = 0; np < 4; np++) {
                uint32_t bd = kS + (uint32_t)((np * 16 + bRow) * APH + kb + bColSel) * 2u;
                LDSM_X4(bf[2 * np][0], bf[2 * np][1], bf[2 * np + 1][0], bf[2 * np + 1][1], bd);
            }
#pragma unroll
            for (int mt = 0; mt < 2; mt++)
#pragma unroll
                for (int nt = 0; nt < 8; nt++)
                    MMA_F16(sacc[mt][nt], qf[kk][mt], bf[nt]);
        }

        // ---- causal mask + quad row max (per mt) ----
        float tmax[2][2] = {{-1e30f, -1e30f}, {-1e30f, -1e30f}};
#pragma unroll
        for (int mt = 0; mt < 2; mt++)
#pragma unroll
            for (int nt = 0; nt < 8; nt++) {
                int col = k0 + nt * 8 + 2 * tig;
                if (col     > rg[mt][0]) sacc[mt][nt][0] = -1e30f;
                if (col + 1 > rg[mt][0]) sacc[mt][nt][1] = -1e30f;
                if (col     > rg[mt][1]) sacc[mt][nt][2] = -1e30f;
                if (col + 1 > rg[mt][1]) sacc[mt][nt][3] = -1e30f;
                tmax[mt][0] = fmaxf(tmax[mt][0], fmaxf(sacc[mt][nt][0], sacc[mt][nt][1]));
                tmax[mt][1] = fmaxf(tmax[mt][1], fmaxf(sacc[mt][nt][2], sacc[mt][nt][3]));
            }
#pragma unroll
        for (int d = 1; d <= 2; d <<= 1)
#pragma unroll
            for (int mt = 0; mt < 2; mt++) {
                tmax[mt][0] = fmaxf(tmax[mt][0], __shfl_xor_sync(0xffffffffu, tmax[mt][0], d));
                tmax[mt][1] = fmaxf(tmax[mt][1], __shfl_xor_sync(0xffffffffu, tmax[mt][1], d));
            }

        float cr[2][2];
#pragma unroll
        for (int mt = 0; mt < 2; mt++)
#pragma unroll
            for (int j = 0; j < 2; j++) {
                float mn = fmaxf(m[mt][j], tmax[mt][j]);
                cr[mt][j] = exp2f(m[mt][j] - mn);
                l[mt][j] *= cr[mt][j];
                m[mt][j] = mn;
            }
#pragma unroll
        for (int mt = 0; mt < 2; mt++)
#pragma unroll
            for (int nt = 0; nt < 8; nt++) {
                oacc[mt][nt][0] *= cr[mt][0]; oacc[mt][nt][1] *= cr[mt][0];
                oacc[mt][nt][2] *= cr[mt][1]; oacc[mt][nt][3] *= cr[mt][1];
            }

        // ---- P = 2^(S-m) via ex2.f16x2; partial l; store P ----
        __syncwarp();
#pragma unroll
        for (int mt = 0; mt < 2; mt++)
#pragma unroll
            for (int nt = 0; nt < 8; nt++) {
                __half2 h01 = __floats2half2_rn(sacc[mt][nt][0] - m[mt][0],
                                                sacc[mt][nt][1] - m[mt][0]);
                __half2 h23 = __floats2half2_rn(sacc[mt][nt][2] - m[mt][1],
                                                sacc[mt][nt][3] - m[mt][1]);
                __half2 p01 = h2exp2(h01);
                __half2 p23 = h2exp2(h23);
                int col = nt * 8 + 2 * tig;
                *(__half2*)&Ps[(wrow + mt * 16 + gid    ) * APH + col] = p01;
                *(__half2*)&Ps[(wrow + mt * 16 + gid + 8) * APH + col] = p23;
                l[mt][0] += h2sum(p01);
                l[mt][1] += h2sum(p23);
            }
        __syncwarp();

        // ---- O += P @ V, V frags reused across mt ----
#pragma unroll
        for (int kk = 0; kk < 4; kk++) {
            const int kb = kk * 16;
            uint32_t a[2][4];
#pragma unroll
            for (int mt = 0; mt < 2; mt++) {
                uint32_t ad = psS +
                    (uint32_t)((wrow + mt * 16 + aRow) * APH + kb + aColSel) * 2u;
                LDSM_X4(a[mt][0], a[mt][1], a[mt][2], a[mt][3], ad);
            }
            uint32_t bv[8][2];
#pragma unroll
            for (int np = 0; np < 4; np++) {
                uint32_t vd = vS + (uint32_t)((kb + vRow) * APH + np * 16 + vColSel) * 2u;
                LDSM_X4_T(bv[2 * np][0], bv[2 * np][1], bv[2 * np + 1][0], bv[2 * np + 1][1], vd);
            }
#pragma unroll
            for (int mt = 0; mt < 2; mt++)
#pragma unroll
                for (int nt = 0; nt < 8; nt++)
                    MMA_F16(oacc[mt][nt], a[mt], bv[nt]);
        }
    }

    // ---- quad-reduce partial row sums, normalize, store half y ----
#pragma unroll
    for (int d = 1; d <= 2; d <<= 1)
#pragma unroll
        for (int mt = 0; mt < 2; mt++) {
            l[mt][0] += __shfl_xor_sync(0xffffffffu, l[mt][0], d);
            l[mt][1] += __shfl_xor_sync(0xffffffffu, l[mt][1], d);
        }
#pragma unroll
    for (int mt = 0; mt < 2; mt++) {
        float inv0 = 1.f / l[mt][0], inv1 = 1.f / l[mt][1];
        __half* y0 = y + (size_t)(b * TSEQ + rg[mt][0]) * DMODEL + h * HDIM;
        __half* y1 = y + (size_t)(b * TSEQ + rg[mt][1]) * DMODEL + h * HDIM;
#pragma unroll
        for (int nt = 0; nt < 8; nt++) {
            int col = nt * 8 + 2 * tig;
            *(__half2*)(y0 + col) = __floats2half2_rn(oacc[mt][nt][0] * inv0,
                                                      oacc[mt][nt][1] * inv0);
            *(__half2*)(y1 + col) = __floats2half2_rn(oacc[mt][nt][2] * inv1,
                                                      oacc[mt][nt][3] * inv1);
        }
    }
}

// ---------------------------------------------------------------------------
extern "C" void kernel_launch(void* const* d_in, const int* in_sizes, int n_in,
                              void* d_out, int out_size)
{
    (void)in_sizes; (void)n_in; (void)out_size;
    const float* x     = (const float*)d_in[0];
    const float* qkv_w = (const float*)d_in[1];
    const float* qkv_b = (const float*)d_in[2];
    const float* o_w   = (const float*)d_in[3];
    const float* o_b   = (const float*)d_in[4];
    float* out = (float*)d_out;

    __half *xh, *qkvh, *yh, *wqkvh, *woh;
    cudaGetSymbolAddress((void**)&xh, g_xh);
    cudaGetSymbolAddress((void**)&qkvh, g_qkvh);
    cudaGetSymbolAddress((void**)&yh, g_yh);
    cudaGetSymbolAddress((void**)&wqkvh, g_wqkvh);
    cudaGetSymbolAddress((void**)&woh, g_woh);

    cudaFuncSetAttribute(gemm_h_kernel<__half>,
                         cudaFuncAttributeMaxDynamicSharedMemorySize, HSMEM_BYTES);
    cudaFuncSetAttribute(gemm_h_kernel<float>,
                         cudaFuncAttributeMaxDynamicSharedMemorySize, HSMEM_BYTES);
    cudaFuncSetAttribute(attn_h_kernel,
                         cudaFuncAttributeMaxDynamicSharedMemorySize, ATT_SMEM_BYTES);

    // prep: single fused fp32 -> fp16 conversion (x, qkv_w, o_w)
    f2h3_kernel<<<1480, 256>>>(x, xh, MROWS * DMODEL / 4,
                               qkv_w, wqkvh, KDIM * D3 / 4,
                               o_w, woh, KDIM * DMODEL / 4);

    // 1) QKV projection
    gemm_h_kernel<__half><<<dim3(D3 / 128, MROWS / 128), 256, HSMEM_BYTES>>>(
        xh, wqkvh, qkv_b, qkvh, D3);

    // 2) causal flash attention (256 q-rows per CTA)
    attn_h_kernel<<<dim3(TSEQ / ABM, NBATCH * NHEADS), 256, ATT_SMEM_BYTES>>>(
        qkvh, yh);

    // 3) output projection
    gemm_h_kernel<float><<<dim3(DMODEL / 128, MROWS / 128), 256, HSMEM_BYTES>>>(
        yh, woh, o_b, out, DMODEL);
}

// round 13
// speedup vs baseline: 1.0434x; 1.0434x over previous
#include <cuda_runtime.h>
#include <cuda_fp16.h>
#include <cstdint>
#include <math.h>

#define NBATCH 4
#define TSEQ   2048
#define DMODEL 1024
#define NHEADS 16
#define HDIM   64
#define MROWS  (NBATCH * TSEQ)   // 8192
#define KDIM   DMODEL            // 1024
#define D3     (3 * DMODEL)

// ---------------- scratch (static device globals; no runtime alloc) --------
__device__ __align__(1024) __half g_xh[(size_t)MROWS * DMODEL];        // 16 MB
__device__ __align__(1024) __half g_qkvh[(size_t)MROWS * D3];          // 50 MB
__device__ __align__(1024) __half g_yh[(size_t)MROWS * DMODEL];        // 16 MB
__device__ __align__(1024) __half g_wqkvh[(size_t)KDIM * D3];          // 6 MB
__device__ __align__(1024) __half g_woh[(size_t)KDIM * DMODEL];        // 2 MB

// ---------------- helpers ---------------------------------------------------
#define CP_ASYNC16(dst, src) \
    asm volatile("cp.async.cg.shared.global [%0], [%1], 16;" \
                 :: "r"(dst), "l"(src) : "memory")
#define CP_COMMIT() asm volatile("cp.async.commit_group;" ::: "memory")
#define CP_WAIT1()  asm volatile("cp.async.wait_group 1;" ::: "memory")

__device__ __forceinline__ uint32_t smem_u32(const void* p) {
    uint32_t a;
    asm("{ .reg .u64 t; cvta.to.shared.u64 t, %1; cvt.u32.u64 %0, t; }"
        : "=r"(a) : "l"(p));
    return a;
}

#define MMA_F16(d, a, b) \
    asm volatile("mma.sync.aligned.m16n8k16.row.col.f32.f16.f16.f32 " \
        "{%0,%1,%2,%3}, {%4,%5,%6,%7}, {%8,%9}, {%0,%1,%2,%3};" \
        : "+f"((d)[0]), "+f"((d)[1]), "+f"((d)[2]), "+f"((d)[3]) \
        : "r"((a)[0]), "r"((a)[1]), "r"((a)[2]), "r"((a)[3]), \
          "r"((b)[0]), "r"((b)[1]))

#define LDSM_X4(r0, r1, r2, r3, addr) \
    asm volatile("ldmatrix.sync.aligned.m8n8.x4.shared.b16 {%0,%1,%2,%3}, [%4];" \
        : "=r"(r0), "=r"(r1), "=r"(r2), "=r"(r3) : "r"(addr))
#define LDSM_X4_T(r0, r1, r2, r3, addr) \
    asm volatile("ldmatrix.sync.aligned.m8n8.x4.trans.shared.b16 {%0,%1,%2,%3}, [%4];" \
        : "=r"(r0), "=r"(r1), "=r"(r2), "=r"(r3) : "r"(addr))

__device__ __forceinline__ void store_pair(float* p, float a, float b) {
    *(float2*)p = make_float2(a, b);
}
__device__ __forceinline__ void store_pair(__half* p, float a, float b) {
    *(__half2*)p = __floats2half2_rn(a, b);
}

__device__ __forceinline__ float h2sum(__half2 v) {
    return __half2float(__hadd(__low2half(v), __high2half(v)));
}

// ---------------- prep: fused fp32 -> fp16 convert (3 segments) ------------
__global__ void f2h3_kernel(const float* __restrict__ in0, __half* __restrict__ out0, int n0,
                            const float* __restrict__ in1, __half* __restrict__ out1, int n1,
                            const float* __restrict__ in2, __half* __restrict__ out2, int n2)
{
    const int ntot = n0 + n1 + n2;
    for (int i = blockIdx.x * blockDim.x + threadIdx.x; i < ntot;
         i += gridDim.x * blockDim.x) {
        const float* in; __half* out; int j = i;
        if (j < n0)            { in = in0; out = out0; }
        else if ((j -= n0) < n1) { in = in1; out = out1; }
        else                   { j -= n1; in = in2; out = out2; }
        float4 v = *(const float4*)(in + (size_t)j * 4);
        __half2 h0 = __floats2half2_rn(v.x, v.y);
        __half2 h1 = __floats2half2_rn(v.z, v.w);
        *(uint2*)(out + (size_t)j * 4) =
            make_uint2(*(uint32_t*)&h0, *(uint32_t*)&h1);
    }
}

// ---------------- fp16 mma GEMM (unchanged from R9/R10/R11) ----------------
#define GBK 64
#define GAP 72
#define GBP 136
#define ATILE_H (128 * GAP)
#define BTILE_H (GBK * GBP)
#define STAGE_H (ATILE_H + BTILE_H)
#define HSMEM_BYTES (3 * STAGE_H * 2)        // 107520 B
#define GCHUNKS (KDIM / GBK)                 // 16

template <typename OutT>
__global__ __launch_bounds__(256, 2) void gemm_h_kernel(
    const __half* __restrict__ A, const __half* __restrict__ W,
    const float* __restrict__ bias, OutT* __restrict__ C, int N)
{
    extern __shared__ __half hsm[];
    const int tid = threadIdx.x;
    const int wid = tid >> 5;
    const int lane = tid & 31;
    const int gid = lane >> 2;
    const int tig = lane & 3;

    const size_t row0 = (size_t)blockIdx.y * 128;
    const size_t col0 = (size_t)blockIdx.x * 128;
    const int wm0 = (wid & 3) * 32;
    const int wn0 = (wid >> 2) * 64;

    const __half* Ab = A + row0 * KDIM;

    float acc[2][8][4];
#pragma unroll
    for (int mt = 0; mt < 2; mt++)
#pragma unroll
        for (int nt = 0; nt < 8; nt++)
#pragma unroll
            for (int j = 0; j < 4; j++) acc[mt][nt][j] = 0.f;

    const uint32_t sbase = smem_u32(hsm);

    const int aRow = lane & 15, aColSel = (lane >> 4) * 8;
    const int tRow = (lane & 7) + (((lane >> 3) & 1) << 3);
    const int tColSel = (lane >> 4) * 8;

    auto load_stage = [&](int s, int chunk) {
        const int kof = chunk * GBK;
        uint32_t aS = sbase + (uint32_t)(s * STAGE_H) * 2u;
        uint32_t bS = aS + (uint32_t)ATILE_H * 2u;
#pragma unroll
        for (int i = 0; i < 4; i++) {
            int idx = tid + i * 256;
            int r = idx >> 3, ch = idx & 7;
            CP_ASYNC16(aS + (uint32_t)(r * GAP + ch * 8) * 2u,
                       Ab + (size_t)r * KDIM + kof + ch * 8);
        }
#pragma unroll
        for (int i = 0; i < 4; i++) {
            int idx = tid + i * 256;
            int r = idx >> 4, ch = idx & 15;
            CP_ASYNC16(bS + (uint32_t)(r * GBP + ch * 8) * 2u,
                       W + (size_t)(kof + r) * N + col0 + ch * 8);
        }
    };

    load_stage(0, 0); CP_COMMIT();
    load_stage(1, 1); CP_COMMIT();

    for (int c = 0; c < GCHUNKS; c++) {
        CP_WAIT1();
        __syncthreads();
        if (c + 2 < GCHUNKS) load_stage((c + 2) % 3, c + 2);
        CP_COMMIT();

        const uint32_t aS = sbase + (uint32_t)((c % 3) * STAGE_H) * 2u;
        const uint32_t bS = aS + (uint32_t)ATILE_H * 2u;
#pragma unroll
        for (int kk = 0; kk < 4; kk++) {
            const int kb = kk * 16;
            uint32_t a[2][4];
#pragma unroll
            for (int mt = 0; mt < 2; mt++) {
                uint32_t ad = aS + (uint32_t)((wm0 + mt * 16 + aRow) * GAP + kb + aColSel) * 2u;
                LDSM_X4(a[mt][0], a[mt][1], a[mt][2], a[mt][3], ad);
            }
            uint32_t b[8][2];
#pragma unroll
            for (int np = 0; np < 4; np++) {
                uint32_t bd = bS + (uint32_t)((kb + tRow) * GBP + wn0 + np * 16 + tColSel) * 2u;
                LDSM_X4_T(b[2 * np][0], b[2 * np][1], b[2 * np + 1][0], b[2 * np + 1][1], bd);
            }
#pragma unroll
            for (int mt = 0; mt < 2; mt++)
#pragma unroll
                for (int nt = 0; nt < 8; nt++)
                    MMA_F16(acc[mt][nt], a[mt], b[nt]);
        }
    }

#pragma unroll
    for (int mt = 0; mt < 2; mt++) {
        size_t r = row0 + wm0 + mt * 16 + gid;
#pragma unroll
        for (int nt = 0; nt < 8; nt++) {
            size_t col = col0 + wn0 + nt * 8 + tig * 2;
            float2 bb = *(const float2*)(bias + col);
            store_pair(C + r * N + col, acc[mt][nt][0] + bb.x, acc[mt][nt][1] + bb.y);
            store_pair(C + (r + 8) * N + col, acc[mt][nt][2] + bb.x, acc[mt][nt][3] + bb.y);
        }
    }
}

// ---------------- fp16 flash attention: R11 body, 3-stage K/V pipe ---------
// Per CTA one (b, h, 128-q tile); 8 warps x 16 q-rows; 64-key tiles.
// K/V triple-buffered via cp.async with wait_group 1 (unconditional commit
// per iter keeps group counting aligned at the tail): each tile's load gets
// ~2 compute phases of latency budget. log2-domain f16x2 softmax (R11).
#define APH 72
#define KVT_H (64 * APH)
#define ATT_SMEM_BYTES ((6 * KVT_H + 128 * APH) * 2)   // 73728 B

__global__ __launch_bounds__(256, 2) void attn_h_kernel(
    const __half* __restrict__ qkv, __half* __restrict__ y)
{
    extern __shared__ __half dsm[];
    __half* Ps = dsm + 6 * KVT_H;

    const int qb  = gridDim.x - 1 - blockIdx.x;
    const int bh  = blockIdx.y;
    const int b   = bh >> 4;
    const int h   = bh & 15;
    const int tid = threadIdx.x;
    const int wid = tid >> 5;
    const int lane = tid & 31;
    const int gid = lane >> 2;
    const int tig = lane & 3;
    const int wrow = wid * 16;
    const int q0 = qb * 128;

    const __half* base = qkv + (size_t)b * TSEQ * D3;
    const uint32_t smS = smem_u32(dsm);
    const uint32_t psS = smem_u32(Ps);

    const int aRow = lane & 15, aColSel = (lane >> 4) * 8;
    const int bRow = (lane & 7) + ((lane >> 4) << 3);
    const int bColSel = ((lane >> 3) & 1) * 8;
    const int vRow = (lane & 7) + (((lane >> 3) & 1) << 3);
    const int vColSel = (lane >> 4) * 8;

    const int ntiles = (qb + 1) * 2;

    auto load_kv = [&](int t, int s) {
        const int k0 = t * 64;
        uint32_t kS = smS + (uint32_t)(s * 2 * KVT_H) * 2u;
        uint32_t vS = kS + (uint32_t)KVT_H * 2u;
        const __half* kb_ = base + (size_t)k0 * D3 + DMODEL + h * HDIM;
#pragma unroll
        for (int i = 0; i < 2; i++) {
            int idx = tid + i * 256;
            int r = idx >> 3, ch = idx & 7;
            uint32_t off = (uint32_t)(r * APH + ch * 8) * 2u;
            const __half* src = kb_ + (size_t)r * D3 + ch * 8;
            CP_ASYNC16(kS + off, src);
            CP_ASYNC16(vS + off, src + DMODEL);
        }
    };

    // prologue: tiles 0 and 1 in flight; stage Q (scaled, log2 domain)
    load_kv(0, 0); CP_COMMIT();
    if (1 < ntiles) load_kv(1, 1);
    CP_COMMIT();

    {
        const __half2 s = __float2half2_rn(0.125f * 1.44269504089f);
#pragma unroll
        for (int i = 0; i < 4; i++) {
            int idx = tid + i * 256;
            int r = idx >> 3, c8 = (idx & 7) << 3;
            uint4 v = *(const uint4*)(base + (size_t)(q0 + r) * D3 + h * HDIM + c8);
            __half2* h2 = reinterpret_cast<__half2*>(&v);
            h2[0] = __hmul2(h2[0], s); h2[1] = __hmul2(h2[1], s);
            h2[2] = __hmul2(h2[2], s); h2[3] = __hmul2(h2[3], s);
            *(uint4*)&Ps[r * APH + c8] = v;
        }
    }
    __syncthreads();

    uint32_t qf[4][4];
#pragma unroll
    for (int kk = 0; kk < 4; kk++) {
        uint32_t ad = psS + (uint32_t)((wrow + aRow) * APH + kk * 16 + aColSel) * 2u;
        LDSM_X4(qf[kk][0], qf[kk][1], qf[kk][2], qf[kk][3], ad);
    }

    const int r0g = q0 + wrow + gid;
    const int r1g = r0g + 8;

    float m0 = -1e30f, m1 = -1e30f, l0 = 0.f, l1 = 0.f;
    float oacc[8][4];
#pragma unroll
    for (int nt = 0; nt < 8; nt++)
#pragma unroll
        for (int j = 0; j < 4; j++) oacc[nt][j] = 0.f;

    for (int t = 0; t < ntiles; t++) {
        const int k0 = t * 64;
        CP_WAIT1();                 // all groups except newest done => tile t ready
        __syncthreads();            // + compute t-1 finished (stage (t+2)%3 reusable)
        if (t + 2 < ntiles) load_kv(t + 2, (t + 2) % 3);
        CP_COMMIT();                // unconditional: keeps group counting aligned

        if (k0 > q0 + wrow + 15) continue;   // warp fully masked

        const uint32_t kS = smS + (uint32_t)((t % 3) * 2 * KVT_H) * 2u;
        const uint32_t vS = kS + (uint32_t)KVT_H * 2u;

        // ---- S = Q @ K^T (log2 domain) ----
        float sacc[8][4];
#pragma unroll
        for (int nt = 0; nt < 8; nt++)
#pragma unroll
            for (int j = 0; j < 4; j++) sacc[nt][j] = 0.f;
#pragma unroll
        for (int kk = 0; kk < 4; kk++) {
            const int kb = kk * 16;
            uint32_t bf[8][2];
#pragma unroll
            for (int np = 0; np < 4; np++) {
                uint32_t bd = kS + (uint32_t)((np * 16 + bRow) * APH + kb + bColSel) * 2u;
                LDSM_X4(bf[2 * np][0], bf[2 * np][1], bf[2 * np + 1][0], bf[2 * np + 1][1], bd);
            }
#pragma unroll
            for (int nt = 0; nt < 8; nt++)
                MMA_F16(sacc[nt], qf[kk], bf[nt]);
        }

        // ---- causal mask + quad row max ----
        float tmax0 = -1e30f, tmax1 = -1e30f;
#pragma unroll
        for (int nt = 0; nt < 8; nt++) {
            int col = k0 + nt * 8 + 2 * tig;
            if (col     > r0g) sacc[nt][0] = -1e30f;
            if (col + 1 > r0g) sacc[nt][1] = -1e30f;
            if (col     > r1g) sacc[nt][2] = -1e30f;
            if (col + 1 > r1g) sacc[nt][3] = -1e30f;
            tmax0 = fmaxf(tmax0, fmaxf(sacc[nt][0], sacc[nt][1]));
            tmax1 = fmaxf(tmax1, fmaxf(sacc[nt][2], sacc[nt][3]));
        }
#pragma unroll
        for (int d = 1; d <= 2; d <<= 1) {
            tmax0 = fmaxf(tmax0, __shfl_xor_sync(0xffffffffu, tmax0, d));
            tmax1 = fmaxf(tmax1, __shfl_xor_sync(0xffffffffu, tmax1, d));
        }

        float mn0 = fmaxf(m0, tmax0), mn1 = fmaxf(m1, tmax1);
        float c0 = exp2f(m0 - mn0), c1 = exp2f(m1 - mn1);
        l0 *= c0; l1 *= c1; m0 = mn0; m1 = mn1;
#pragma unroll
        for (int nt = 0; nt < 8; nt++) {
            oacc[nt][0] *= c0; oacc[nt][1] *= c0;
            oacc[nt][2] *= c1; oacc[nt][3] *= c1;
        }

        // ---- P = 2^(S - m) via ex2.approx.f16x2; l from same half values ----
        __syncwarp();
#pragma unroll
        for (int nt = 0; nt < 8; nt++) {
            __half2 h01 = __floats2half2_rn(sacc[nt][0] - m0, sacc[nt][1] - m0);
            __half2 h23 = __floats2half2_rn(sacc[nt][2] - m1, sacc[nt][3] - m1);
            __half2 p01 = h2exp2(h01);
            __half2 p23 = h2exp2(h23);
            int col = nt * 8 + 2 * tig;
            *(__half2*)&Ps[(wrow + gid    ) * APH + col] = p01;
            *(__half2*)&Ps[(wrow + gid + 8) * APH + col] = p23;
            l0 += h2sum(p01);
            l1 += h2sum(p23);
        }
        __syncwarp();

        // ---- O += P @ V ----
#pragma unroll
        for (int kk = 0; kk < 4; kk++) {
            const int kb = kk * 16;
            uint32_t a[4];
            {
                uint32_t ad = psS + (uint32_t)((wrow + aRow) * APH + kb + aColSel) * 2u;
                LDSM_X4(a[0], a[1], a[2], a[3], ad);
            }
            uint32_t bv[8][2];
#pragma unroll
            for (int np = 0; np < 4; np++) {
                uint32_t vd = vS + (uint32_t)((kb + vRow) * APH + np * 16 + vColSel) * 2u;
                LDSM_X4_T(bv[2 * np][0], bv[2 * np][1], bv[2 * np + 1][0], bv[2 * np + 1][1], vd);
            }
#pragma unroll
            for (int nt = 0; nt < 8; nt++)
                MMA_F16(oacc[nt], a, bv[nt]);
        }
    }

    // ---- quad-reduce partial row sums, normalize, store half y ----
#pragma unroll
    for (int d = 1; d <= 2; d <<= 1) {
        l0 += __shfl_xor_sync(0xffffffffu, l0, d);
        l1 += __shfl_xor_sync(0xffffffffu, l1, d);
    }
    float inv0 = 1.f / l0, inv1 = 1.f / l1;
    __half* y0 = y + (size_t)(b * TSEQ + r0g) * DMODEL + h * HDIM;
    __half* y1 = y + (size_t)(b * TSEQ + r1g) * DMODEL + h * HDIM;
#pragma unroll
    for (int nt = 0; nt < 8; nt++) {
        int col = nt * 8 + 2 * tig;
        *(__half2*)(y0 + col) = __floats2half2_rn(oacc[nt][0] * inv0, oacc[nt][1] * inv0);
        *(__half2*)(y1 + col) = __floats2half2_rn(oacc[nt][2] * inv1, oacc[nt][3] * inv1);
    }
}

// ---------------------------------------------------------------------------
extern "C" void kernel_launch(void* const* d_in, const int* in_sizes, int n_in,
                              void* d_out, int out_size)
{
    (void)in_sizes; (void)n_in; (void)out_size;
    const float* x     = (const float*)d_in[0];
    const float* qkv_w = (const float*)d_in[1];
    const float* qkv_b = (const float*)d_in[2];
    const float* o_w   = (const float*)d_in[3];
    const float* o_b   = (const float*)d_in[4];
    float* out = (float*)d_out;

    __half *xh, *qkvh, *yh, *wqkvh, *woh;
    cudaGetSymbolAddress((void**)&xh, g_xh);
    cudaGetSymbolAddress((void**)&qkvh, g_qkvh);
    cudaGetSymbolAddress((void**)&yh, g_yh);
    cudaGetSymbolAddress((void**)&wqkvh, g_wqkvh);
    cudaGetSymbolAddress((void**)&woh, g_woh);

    cudaFuncSetAttribute(gemm_h_kernel<__half>,
                         cudaFuncAttributeMaxDynamicSharedMemorySize, HSMEM_BYTES);
    cudaFuncSetAttribute(gemm_h_kernel<float>,
                         cudaFuncAttributeMaxDynamicSharedMemorySize, HSMEM_BYTES);
    cudaFuncSetAttribute(attn_h_kernel,
                         cudaFuncAttributeMaxDynamicSharedMemorySize, ATT_SMEM_BYTES);

    // prep: single fused fp32 -> fp16 conversion (x, qkv_w, o_w)
    f2h3_kernel<<<1480, 256>>>(x, xh, MROWS * DMODEL / 4,
                               qkv_w, wqkvh, KDIM * D3 / 4,
                               o_w, woh, KDIM * DMODEL / 4);

    // 1) QKV projection
    gemm_h_kernel<__half><<<dim3(D3 / 128, MROWS / 128), 256, HSMEM_BYTES>>>(
        xh, wqkvh, qkv_b, qkvh, D3);

    // 2) causal flash attention
    attn_h_kernel<<<dim3(TSEQ / 128, NBATCH * NHEADS), 256, ATT_SMEM_BYTES>>>(
        qkvh, yh);

    // 3) output projection
    gemm_h_kernel<float><<<dim3(DMODEL / 128, MROWS / 128), 256, HSMEM_BYTES>>>(
        yh, woh, o_b, out, DMODEL);
}

// round 14
// speedup vs baseline: 1.0709x; 1.0264x over previous
#include <cuda_runtime.h>
#include <cuda_fp16.h>
#include <cstdint>
#include <math.h>

#define NBATCH 4
#define TSEQ   2048
#define DMODEL 1024
#define NHEADS 16
#define HDIM   64
#define MROWS  (NBATCH * TSEQ)   // 8192
#define KDIM   DMODEL            // 1024
#define D3     (3 * DMODEL)

// ---------------- scratch (static device globals; no runtime alloc) --------
__device__ __align__(1024) __half g_xh[(size_t)MROWS * DMODEL];        // 16 MB
__device__ __align__(1024) __half g_qkvh[(size_t)MROWS * D3];          // 50 MB
__device__ __align__(1024) __half g_yh[(size_t)MROWS * DMODEL];        // 16 MB
__device__ __align__(1024) __half g_wqkvh[(size_t)KDIM * D3];          // 6 MB
__device__ __align__(1024) __half g_woh[(size_t)KDIM * DMODEL];        // 2 MB

// ---------------- helpers ---------------------------------------------------
#define CP_ASYNC16(dst, src) \
    asm volatile("cp.async.cg.shared.global [%0], [%1], 16;" \
                 :: "r"(dst), "l"(src) : "memory")
#define CP_COMMIT() asm volatile("cp.async.commit_group;" ::: "memory")
#define CP_WAIT1()  asm volatile("cp.async.wait_group 1;" ::: "memory")
#define CP_WAIT0()  asm volatile("cp.async.wait_group 0;" ::: "memory")

__device__ __forceinline__ uint32_t smem_u32(const void* p) {
    uint32_t a;
    asm("{ .reg .u64 t; cvta.to.shared.u64 t, %1; cvt.u32.u64 %0, t; }"
        : "=r"(a) : "l"(p));
    return a;
}

#define MMA_F16(d, a, b) \
    asm volatile("mma.sync.aligned.m16n8k16.row.col.f32.f16.f16.f32 " \
        "{%0,%1,%2,%3}, {%4,%5,%6,%7}, {%8,%9}, {%0,%1,%2,%3};" \
        : "+f"((d)[0]), "+f"((d)[1]), "+f"((d)[2]), "+f"((d)[3]) \
        : "r"((a)[0]), "r"((a)[1]), "r"((a)[2]), "r"((a)[3]), \
          "r"((b)[0]), "r"((b)[1]))

#define LDSM_X4(r0, r1, r2, r3, addr) \
    asm volatile("ldmatrix.sync.aligned.m8n8.x4.shared.b16 {%0,%1,%2,%3}, [%4];" \
        : "=r"(r0), "=r"(r1), "=r"(r2), "=r"(r3) : "r"(addr))
#define LDSM_X4_T(r0, r1, r2, r3, addr) \
    asm volatile("ldmatrix.sync.aligned.m8n8.x4.trans.shared.b16 {%0,%1,%2,%3}, [%4];" \
        : "=r"(r0), "=r"(r1), "=r"(r2), "=r"(r3) : "r"(addr))

__device__ __forceinline__ void store_pair(float* p, float a, float b) {
    *(float2*)p = make_float2(a, b);
}
__device__ __forceinline__ void store_pair(__half* p, float a, float b) {
    *(__half2*)p = __floats2half2_rn(a, b);
}

__device__ __forceinline__ float h2sum(__half2 v) {
    return __half2float(__hadd(__low2half(v), __high2half(v)));
}

// ---------------- prep: fused fp32 -> fp16 convert (3 segments) ------------
__global__ void f2h3_kernel(const float* __restrict__ in0, __half* __restrict__ out0, int n0,
                            const float* __restrict__ in1, __half* __restrict__ out1, int n1,
                            const float* __restrict__ in2, __half* __restrict__ out2, int n2)
{
    const int ntot = n0 + n1 + n2;
    for (int i = blockIdx.x * blockDim.x + threadIdx.x; i < ntot;
         i += gridDim.x * blockDim.x) {
        const float* in; __half* out; int j = i;
        if (j < n0)            { in = in0; out = out0; }
        else if ((j -= n0) < n1) { in = in1; out = out1; }
        else                   { j -= n1; in = in2; out = out2; }
        float4 v = *(const float4*)(in + (size_t)j * 4);
        __half2 h0 = __floats2half2_rn(v.x, v.y);
        __half2 h1 = __floats2half2_rn(v.z, v.w);
        *(uint2*)(out + (size_t)j * 4) =
            make_uint2(*(uint32_t*)&h0, *(uint32_t*)&h1);
    }
}

// ---------------- fp16 mma GEMM (unchanged from R9/R10/R11) ----------------
#define GBK 64
#define GAP 72
#define GBP 136
#define ATILE_H (128 * GAP)
#define BTILE_H (GBK * GBP)
#define STAGE_H (ATILE_H + BTILE_H)
#define HSMEM_BYTES (3 * STAGE_H * 2)        // 107520 B
#define GCHUNKS (KDIM / GBK)                 // 16

template <typename OutT>
__global__ __launch_bounds__(256, 2) void gemm_h_kernel(
    const __half* __restrict__ A, const __half* __restrict__ W,
    const float* __restrict__ bias, OutT* __restrict__ C, int N)
{
    extern __shared__ __half hsm[];
    const int tid = threadIdx.x;
    const int wid = tid >> 5;
    const int lane = tid & 31;
    const int gid = lane >> 2;
    const int tig = lane & 3;

    const size_t row0 = (size_t)blockIdx.y * 128;
    const size_t col0 = (size_t)blockIdx.x * 128;
    const int wm0 = (wid & 3) * 32;
    const int wn0 = (wid >> 2) * 64;

    const __half* Ab = A + row0 * KDIM;

    float acc[2][8][4];
#pragma unroll
    for (int mt = 0; mt < 2; mt++)
#pragma unroll
        for (int nt = 0; nt < 8; nt++)
#pragma unroll
            for (int j = 0; j < 4; j++) acc[mt][nt][j] = 0.f;

    const uint32_t sbase = smem_u32(hsm);

    const int aRow = lane & 15, aColSel = (lane >> 4) * 8;
    const int tRow = (lane & 7) + (((lane >> 3) & 1) << 3);
    const int tColSel = (lane >> 4) * 8;

    auto load_stage = [&](int s, int chunk) {
        const int kof = chunk * GBK;
        uint32_t aS = sbase + (uint32_t)(s * STAGE_H) * 2u;
        uint32_t bS = aS + (uint32_t)ATILE_H * 2u;
#pragma unroll
        for (int i = 0; i < 4; i++) {
            int idx = tid + i * 256;
            int r = idx >> 3, ch = idx & 7;
            CP_ASYNC16(aS + (uint32_t)(r * GAP + ch * 8) * 2u,
                       Ab + (size_t)r * KDIM + kof + ch * 8);
        }
#pragma unroll
        for (int i = 0; i < 4; i++) {
            int idx = tid + i * 256;
            int r = idx >> 4, ch = idx & 15;
            CP_ASYNC16(bS + (uint32_t)(r * GBP + ch * 8) * 2u,
                       W + (size_t)(kof + r) * N + col0 + ch * 8);
        }
    };

    load_stage(0, 0); CP_COMMIT();
    load_stage(1, 1); CP_COMMIT();

    for (int c = 0; c < GCHUNKS; c++) {
        CP_WAIT1();
        __syncthreads();
        if (c + 2 < GCHUNKS) load_stage((c + 2) % 3, c + 2);
        CP_COMMIT();

        const uint32_t aS = sbase + (uint32_t)((c % 3) * STAGE_H) * 2u;
        const uint32_t bS = aS + (uint32_t)ATILE_H * 2u;
#pragma unroll
        for (int kk = 0; kk < 4; kk++) {
            const int kb = kk * 16;
            uint32_t a[2][4];
#pragma unroll
            for (int mt = 0; mt < 2; mt++) {
                uint32_t ad = aS + (uint32_t)((wm0 + mt * 16 + aRow) * GAP + kb + aColSel) * 2u;
                LDSM_X4(a[mt][0], a[mt][1], a[mt][2], a[mt][3], ad);
            }
            uint32_t b[8][2];
#pragma unroll
            for (int np = 0; np < 4; np++) {
                uint32_t bd = bS + (uint32_t)((kb + tRow) * GBP + wn0 + np * 16 + tColSel) * 2u;
                LDSM_X4_T(b[2 * np][0], b[2 * np][1], b[2 * np + 1][0], b[2 * np + 1][1], bd);
            }
#pragma unroll
            for (int mt = 0; mt < 2; mt++)
#pragma unroll
                for (int nt = 0; nt < 8; nt++)
                    MMA_F16(acc[mt][nt], a[mt], b[nt]);
        }
    }

#pragma unroll
    for (int mt = 0; mt < 2; mt++) {
        size_t r = row0 + wm0 + mt * 16 + gid;
#pragma unroll
        for (int nt = 0; nt < 8; nt++) {
            size_t col = col0 + wn0 + nt * 8 + tig * 2;
            float2 bb = *(const float2*)(bias + col);
            store_pair(C + r * N + col, acc[mt][nt][0] + bb.x, acc[mt][nt][1] + bb.y);
            store_pair(C + (r + 8) * N + col, acc[mt][nt][2] + bb.x, acc[mt][nt][3] + bb.y);
        }
    }
}

// ---------------- fp16 flash attention: register-resident P ----------------
// R11 structure (2-stage cp.async K/V, log2-domain f16x2 softmax), but P
// never touches SMEM: the softmax C-fragment IS the PV A-fragment —
// a[kk] = {p01[2kk], p23[2kk], p01[2kk+1], p23[2kk+1]}.  Removes per tile
// 16 STS + 4 LDSM + 2 syncwarp and shortens the softmax->PV chain.
#define APH 72
#define KVT_H (64 * APH)
#define ATT_SMEM_BYTES ((4 * KVT_H + 128 * APH) * 2)   // 55296 B

__global__ __launch_bounds__(256, 2) void attn_h_kernel(
    const __half* __restrict__ qkv, __half* __restrict__ y)
{
    extern __shared__ __half dsm[];
    __half* Ps = dsm + 4 * KVT_H;            // Q staging only

    const int qb  = gridDim.x - 1 - blockIdx.x;
    const int bh  = blockIdx.y;
    const int b   = bh >> 4;
    const int h   = bh & 15;
    const int tid = threadIdx.x;
    const int wid = tid >> 5;
    const int lane = tid & 31;
    const int gid = lane >> 2;
    const int tig = lane & 3;
    const int wrow = wid * 16;
    const int q0 = qb * 128;

    const __half* base = qkv + (size_t)b * TSEQ * D3;
    const uint32_t smS = smem_u32(dsm);
    const uint32_t psS = smem_u32(Ps);

    const int aRow = lane & 15, aColSel = (lane >> 4) * 8;
    const int bRow = (lane & 7) + ((lane >> 4) << 3);
    const int bColSel = ((lane >> 3) & 1) * 8;
    const int vRow = (lane & 7) + (((lane >> 3) & 1) << 3);
    const int vColSel = (lane >> 4) * 8;

    const int ntiles = (qb + 1) * 2;

    auto load_kv = [&](int t, int s) {
        const int k0 = t * 64;
        uint32_t kS = smS + (uint32_t)(s * 2 * KVT_H) * 2u;
        uint32_t vS = kS + (uint32_t)KVT_H * 2u;
        const __half* kb_ = base + (size_t)k0 * D3 + DMODEL + h * HDIM;
#pragma unroll
        for (int i = 0; i < 2; i++) {
            int idx = tid + i * 256;
            int r = idx >> 3, ch = idx & 7;
            uint32_t off = (uint32_t)(r * APH + ch * 8) * 2u;
            const __half* src = kb_ + (size_t)r * D3 + ch * 8;
            CP_ASYNC16(kS + off, src);
            CP_ASYNC16(vS + off, src + DMODEL);
        }
    };

    // prologue: kick tile-0 K/V load; stage Q (scaled, log2 domain) meanwhile
    load_kv(0, 0); CP_COMMIT();

    {
        const __half2 s = __float2half2_rn(0.125f * 1.44269504089f);
#pragma unroll
        for (int i = 0; i < 4; i++) {
            int idx = tid + i * 256;
            int r = idx >> 3, c8 = (idx & 7) << 3;
            uint4 v = *(const uint4*)(base + (size_t)(q0 + r) * D3 + h * HDIM + c8);
            __half2* h2 = reinterpret_cast<__half2*>(&v);
            h2[0] = __hmul2(h2[0], s); h2[1] = __hmul2(h2[1], s);
            h2[2] = __hmul2(h2[2], s); h2[3] = __hmul2(h2[3], s);
            *(uint4*)&Ps[r * APH + c8] = v;
        }
    }
    __syncthreads();

    uint32_t qf[4][4];
#pragma unroll
    for (int kk = 0; kk < 4; kk++) {
        uint32_t ad = psS + (uint32_t)((wrow + aRow) * APH + kk * 16 + aColSel) * 2u;
        LDSM_X4(qf[kk][0], qf[kk][1], qf[kk][2], qf[kk][3], ad);
    }

    const int r0g = q0 + wrow + gid;
    const int r1g = r0g + 8;

    float m0 = -1e30f, m1 = -1e30f, l0 = 0.f, l1 = 0.f;
    float oacc[8][4];
#pragma unroll
    for (int nt = 0; nt < 8; nt++)
#pragma unroll
        for (int j = 0; j < 4; j++) oacc[nt][j] = 0.f;

    for (int t = 0; t < ntiles; t++) {
        const int k0 = t * 64;
        CP_WAIT0();
        __syncthreads();
        if (t + 1 < ntiles) { load_kv(t + 1, (t + 1) & 1); CP_COMMIT(); }

        if (k0 > q0 + wrow + 15) continue;   // warp fully masked

        const uint32_t kS = smS + (uint32_t)((t & 1) * 2 * KVT_H) * 2u;
        const uint32_t vS = kS + (uint32_t)KVT_H * 2u;

        // ---- S = Q @ K^T (log2 domain) ----
        float sacc[8][4];
#pragma unroll
        for (int nt = 0; nt < 8; nt++)
#pragma unroll
            for (int j = 0; j < 4; j++) sacc[nt][j] = 0.f;
#pragma unroll
        for (int kk = 0; kk < 4; kk++) {
            const int kb = kk * 16;
            uint32_t bf[8][2];
#pragma unroll
            for (int np = 0; np < 4; np++) {
                uint32_t bd = kS + (uint32_t)((np * 16 + bRow) * APH + kb + bColSel) * 2u;
                LDSM_X4(bf[2 * np][0], bf[2 * np][1], bf[2 * np + 1][0], bf[2 * np + 1][1], bd);
            }
#pragma unroll
            for (int nt = 0; nt < 8; nt++)
                MMA_F16(sacc[nt], qf[kk], bf[nt]);
        }

        // ---- causal mask + quad row max ----
        float tmax0 = -1e30f, tmax1 = -1e30f;
#pragma unroll
        for (int nt = 0; nt < 8; nt++) {
            int col = k0 + nt * 8 + 2 * tig;
            if (col     > r0g) sacc[nt][0] = -1e30f;
            if (col + 1 > r0g) sacc[nt][1] = -1e30f;
            if (col     > r1g) sacc[nt][2] = -1e30f;
            if (col + 1 > r1g) sacc[nt][3] = -1e30f;
            tmax0 = fmaxf(tmax0, fmaxf(sacc[nt][0], sacc[nt][1]));
            tmax1 = fmaxf(tmax1, fmaxf(sacc[nt][2], sacc[nt][3]));
        }
#pragma unroll
        for (int d = 1; d <= 2; d <<= 1) {
            tmax0 = fmaxf(tmax0, __shfl_xor_sync(0xffffffffu, tmax0, d));
            tmax1 = fmaxf(tmax1, __shfl_xor_sync(0xffffffffu, tmax1, d));
        }

        float mn0 = fmaxf(m0, tmax0), mn1 = fmaxf(m1, tmax1);
        float c0 = exp2f(m0 - mn0), c1 = exp2f(m1 - mn1);
        l0 *= c0; l1 *= c1; m0 = mn0; m1 = mn1;
#pragma unroll
        for (int nt = 0; nt < 8; nt++) {
            oacc[nt][0] *= c0; oacc[nt][1] *= c0;
            oacc[nt][2] *= c1; oacc[nt][3] *= c1;
        }

        // ---- P = 2^(S - m) via ex2.approx.f16x2, kept in registers ----
        uint32_t pp01[8], pp23[8];
#pragma unroll
        for (int nt = 0; nt < 8; nt++) {
            __half2 h01 = __floats2half2_rn(sacc[nt][0] - m0, sacc[nt][1] - m0);
            __half2 h23 = __floats2half2_rn(sacc[nt][2] - m1, sacc[nt][3] - m1);
            __half2 p01 = h2exp2(h01);
            __half2 p23 = h2exp2(h23);
            pp01[nt] = *(uint32_t*)&p01;
            pp23[nt] = *(uint32_t*)&p23;
            l0 += h2sum(p01);
            l1 += h2sum(p23);
        }

        // ---- O += P @ V: A-fragment built directly from softmax regs ----
#pragma unroll
        for (int kk = 0; kk < 4; kk++) {
            const int kb = kk * 16;
            uint32_t a[4];
            a[0] = pp01[2 * kk];
            a[1] = pp23[2 * kk];
            a[2] = pp01[2 * kk + 1];
            a[3] = pp23[2 * kk + 1];
            uint32_t bv[8][2];
#pragma unroll
            for (int np = 0; np < 4; np++) {
                uint32_t vd = vS + (uint32_t)((kb + vRow) * APH + np * 16 + vColSel) * 2u;
                LDSM_X4_T(bv[2 * np][0], bv[2 * np][1], bv[2 * np + 1][0], bv[2 * np + 1][1], vd);
            }
#pragma unroll
            for (int nt = 0; nt < 8; nt++)
                MMA_F16(oacc[nt], a, bv[nt]);
        }
    }

    // ---- quad-reduce partial row sums, normalize, store half y ----
#pragma unroll
    for (int d = 1; d <= 2; d <<= 1) {
        l0 += __shfl_xor_sync(0xffffffffu, l0, d);
        l1 += __shfl_xor_sync(0xffffffffu, l1, d);
    }
    float inv0 = 1.f / l0, inv1 = 1.f / l1;
    __half* y0 = y + (size_t)(b * TSEQ + r0g) * DMODEL + h * HDIM;
    __half* y1 = y + (size_t)(b * TSEQ + r1g) * DMODEL + h * HDIM;
#pragma unroll
    for (int nt = 0; nt < 8; nt++) {
        int col = nt * 8 + 2 * tig;
        *(__half2*)(y0 + col) = __floats2half2_rn(oacc[nt][0] * inv0, oacc[nt][1] * inv0);
        *(__half2*)(y1 + col) = __floats2half2_rn(oacc[nt][2] * inv1, oacc[nt][3] * inv1);
    }
}

// ---------------------------------------------------------------------------
extern "C" void kernel_launch(void* const* d_in, const int* in_sizes, int n_in,
                              void* d_out, int out_size)
{
    (void)in_sizes; (void)n_in; (void)out_size;
    const float* x     = (const float*)d_in[0];
    const float* qkv_w = (const float*)d_in[1];
    const float* qkv_b = (const float*)d_in[2];
    const float* o_w   = (const float*)d_in[3];
    const float* o_b   = (const float*)d_in[4];
    float* out = (float*)d_out;

    __half *xh, *qkvh, *yh, *wqkvh, *woh;
    cudaGetSymbolAddress((void**)&xh, g_xh);
    cudaGetSymbolAddress((void**)&qkvh, g_qkvh);
    cudaGetSymbolAddress((void**)&yh, g_yh);
    cudaGetSymbolAddress((void**)&wqkvh, g_wqkvh);
    cudaGetSymbolAddress((void**)&woh, g_woh);

    cudaFuncSetAttribute(gemm_h_kernel<__half>,
                         cudaFuncAttributeMaxDynamicSharedMemorySize, HSMEM_BYTES);
    cudaFuncSetAttribute(gemm_h_kernel<float>,
                         cudaFuncAttributeMaxDynamicSharedMemorySize, HSMEM_BYTES);
    cudaFuncSetAttribute(attn_h_kernel,
                         cudaFuncAttributeMaxDynamicSharedMemorySize, ATT_SMEM_BYTES);

    // prep: single fused fp32 -> fp16 conversion (x, qkv_w, o_w)
    f2h3_kernel<<<1480, 256>>>(x, xh, MROWS * DMODEL / 4,
                               qkv_w, wqkvh, KDIM * D3 / 4,
                               o_w, woh, KDIM * DMODEL / 4);

    // 1) QKV projection
    gemm_h_kernel<__half><<<dim3(D3 / 128, MROWS / 128), 256, HSMEM_BYTES>>>(
        xh, wqkvh, qkv_b, qkvh, D3);

    // 2) causal flash attention
    attn_h_kernel<<<dim3(TSEQ / 128, NBATCH * NHEADS), 256, ATT_SMEM_BYTES>>>(
        qkvh, yh);

    // 3) output projection
    gemm_h_kernel<float><<<dim3(DMODEL / 128, MROWS / 128), 256, HSMEM_BYTES>>>(
        yh, woh, o_b, out, DMODEL);
}

// round 15
// speedup vs baseline: 1.0818x; 1.0102x over previous
#include <cuda_runtime.h>
#include <cuda_fp16.h>
#include <cstdint>
#include <math.h>

#define NBATCH 4
#define TSEQ   2048
#define DMODEL 1024
#define NHEADS 16
#define HDIM   64
#define MROWS  (NBATCH * TSEQ)   // 8192
#define KDIM   DMODEL            // 1024
#define D3     (3 * DMODEL)

// ---------------- scratch (static device globals; no runtime alloc) --------
__device__ __align__(1024) __half g_xh[(size_t)MROWS * DMODEL];        // 16 MB
__device__ __align__(1024) __half g_qkvh[(size_t)MROWS * D3];          // 50 MB
__device__ __align__(1024) __half g_yh[(size_t)MROWS * DMODEL];        // 16 MB
__device__ __align__(1024) __half g_wqkvh[(size_t)KDIM * D3];          // 6 MB
__device__ __align__(1024) __half g_woh[(size_t)KDIM * DMODEL];        // 2 MB

// ---------------- helpers ---------------------------------------------------
#define CP_ASYNC16(dst, src) \
    asm volatile("cp.async.cg.shared.global [%0], [%1], 16;" \
                 :: "r"(dst), "l"(src) : "memory")
#define CP_COMMIT() asm volatile("cp.async.commit_group;" ::: "memory")
#define CP_WAIT1()  asm volatile("cp.async.wait_group 1;" ::: "memory")
#define CP_WAIT0()  asm volatile("cp.async.wait_group 0;" ::: "memory")

__device__ __forceinline__ uint32_t smem_u32(const void* p) {
    uint32_t a;
    asm("{ .reg .u64 t; cvta.to.shared.u64 t, %1; cvt.u32.u64 %0, t; }"
        : "=r"(a) : "l"(p));
    return a;
}

#define MMA_F16(d, a, b) \
    asm volatile("mma.sync.aligned.m16n8k16.row.col.f32.f16.f16.f32 " \
        "{%0,%1,%2,%3}, {%4,%5,%6,%7}, {%8,%9}, {%0,%1,%2,%3};" \
        : "+f"((d)[0]), "+f"((d)[1]), "+f"((d)[2]), "+f"((d)[3]) \
        : "r"((a)[0]), "r"((a)[1]), "r"((a)[2]), "r"((a)[3]), \
          "r"((b)[0]), "r"((b)[1]))

#define LDSM_X4(r0, r1, r2, r3, addr) \
    asm volatile("ldmatrix.sync.aligned.m8n8.x4.shared.b16 {%0,%1,%2,%3}, [%4];" \
        : "=r"(r0), "=r"(r1), "=r"(r2), "=r"(r3) : "r"(addr))
#define LDSM_X4_T(r0, r1, r2, r3, addr) \
    asm volatile("ldmatrix.sync.aligned.m8n8.x4.trans.shared.b16 {%0,%1,%2,%3}, [%4];" \
        : "=r"(r0), "=r"(r1), "=r"(r2), "=r"(r3) : "r"(addr))

__device__ __forceinline__ void store_pair(float* p, float a, float b) {
    *(float2*)p = make_float2(a, b);
}
__device__ __forceinline__ void store_pair(__half* p, float a, float b) {
    *(__half2*)p = __floats2half2_rn(a, b);
}

__device__ __forceinline__ float h2sum(__half2 v) {
    return __half2float(__hadd(__low2half(v), __high2half(v)));
}

// ---------------- prep: fused fp32 -> fp16 convert (3 segments) ------------
__global__ void f2h3_kernel(const float* __restrict__ in0, __half* __restrict__ out0, int n0,
                            const float* __restrict__ in1, __half* __restrict__ out1, int n1,
                            const float* __restrict__ in2, __half* __restrict__ out2, int n2)
{
    const int ntot = n0 + n1 + n2;
    for (int i = blockIdx.x * blockDim.x + threadIdx.x; i < ntot;
         i += gridDim.x * blockDim.x) {
        const float* in; __half* out; int j = i;
        if (j < n0)            { in = in0; out = out0; }
        else if ((j -= n0) < n1) { in = in1; out = out1; }
        else                   { j -= n1; in = in2; out = out2; }
        float4 v = *(const float4*)(in + (size_t)j * 4);
        __half2 h0 = __floats2half2_rn(v.x, v.y);
        __half2 h1 = __floats2half2_rn(v.z, v.w);
        *(uint2*)(out + (size_t)j * 4) =
            make_uint2(*(uint32_t*)&h0, *(uint32_t*)&h1);
    }
}

// ---------------- fp16 mma GEMM (unchanged) --------------------------------
#define GBK 64
#define GAP 72
#define GBP 136
#define ATILE_H (128 * GAP)
#define BTILE_H (GBK * GBP)
#define STAGE_H (ATILE_H + BTILE_H)
#define HSMEM_BYTES (3 * STAGE_H * 2)        // 107520 B
#define GCHUNKS (KDIM / GBK)                 // 16

template <typename OutT>
__global__ __launch_bounds__(256, 2) void gemm_h_kernel(
    const __half* __restrict__ A, const __half* __restrict__ W,
    const float* __restrict__ bias, OutT* __restrict__ C, int N)
{
    extern __shared__ __half hsm[];
    const int tid = threadIdx.x;
    const int wid = tid >> 5;
    const int lane = tid & 31;
    const int gid = lane >> 2;
    const int tig = lane & 3;

    const size_t row0 = (size_t)blockIdx.y * 128;
    const size_t col0 = (size_t)blockIdx.x * 128;
    const int wm0 = (wid & 3) * 32;
    const int wn0 = (wid >> 2) * 64;

    const __half* Ab = A + row0 * KDIM;

    float acc[2][8][4];
#pragma unroll
    for (int mt = 0; mt < 2; mt++)
#pragma unroll
        for (int nt = 0; nt < 8; nt++)
#pragma unroll
            for (int j = 0; j < 4; j++) acc[mt][nt][j] = 0.f;

    const uint32_t sbase = smem_u32(hsm);

    const int aRow = lane & 15, aColSel = (lane >> 4) * 8;
    const int tRow = (lane & 7) + (((lane >> 3) & 1) << 3);
    const int tColSel = (lane >> 4) * 8;

    auto load_stage = [&](int s, int chunk) {
        const int kof = chunk * GBK;
        uint32_t aS = sbase + (uint32_t)(s * STAGE_H) * 2u;
        uint32_t bS = aS + (uint32_t)ATILE_H * 2u;
#pragma unroll
        for (int i = 0; i < 4; i++) {
            int idx = tid + i * 256;
            int r = idx >> 3, ch = idx & 7;
            CP_ASYNC16(aS + (uint32_t)(r * GAP + ch * 8) * 2u,
                       Ab + (size_t)r * KDIM + kof + ch * 8);
        }
#pragma unroll
        for (int i = 0; i < 4; i++) {
            int idx = tid + i * 256;
            int r = idx >> 4, ch = idx & 15;
            CP_ASYNC16(bS + (uint32_t)(r * GBP + ch * 8) * 2u,
                       W + (size_t)(kof + r) * N + col0 + ch * 8);
        }
    };

    load_stage(0, 0); CP_COMMIT();
    load_stage(1, 1); CP_COMMIT();

    for (int c = 0; c < GCHUNKS; c++) {
        CP_WAIT1();
        __syncthreads();
        if (c + 2 < GCHUNKS) load_stage((c + 2) % 3, c + 2);
        CP_COMMIT();

        const uint32_t aS = sbase + (uint32_t)((c % 3) * STAGE_H) * 2u;
        const uint32_t bS = aS + (uint32_t)ATILE_H * 2u;
#pragma unroll
        for (int kk = 0; kk < 4; kk++) {
            const int kb = kk * 16;
            uint32_t a[2][4];
#pragma unroll
            for (int mt = 0; mt < 2; mt++) {
                uint32_t ad = aS + (uint32_t)((wm0 + mt * 16 + aRow) * GAP + kb + aColSel) * 2u;
                LDSM_X4(a[mt][0], a[mt][1], a[mt][2], a[mt][3], ad);
            }
            uint32_t b[8][2];
#pragma unroll
            for (int np = 0; np < 4; np++) {
                uint32_t bd = bS + (uint32_t)((kb + tRow) * GBP + wn0 + np * 16 + tColSel) * 2u;
                LDSM_X4_T(b[2 * np][0], b[2 * np][1], b[2 * np + 1][0], b[2 * np + 1][1], bd);
            }
#pragma unroll
            for (int mt = 0; mt < 2; mt++)
#pragma unroll
                for (int nt = 0; nt < 8; nt++)
                    MMA_F16(acc[mt][nt], a[mt], b[nt]);
        }
    }

#pragma unroll
    for (int mt = 0; mt < 2; mt++) {
        size_t r = row0 + wm0 + mt * 16 + gid;
#pragma unroll
        for (int nt = 0; nt < 8; nt++) {
            size_t col = col0 + wn0 + nt * 8 + tig * 2;
            float2 bb = *(const float2*)(bias + col);
            store_pair(C + r * N + col, acc[mt][nt][0] + bb.x, acc[mt][nt][1] + bb.y);
            store_pair(C + (r + 8) * N + col, acc[mt][nt][2] + bb.x, acc[mt][nt][3] + bb.y);
        }
    }
}

// ---------------- fp16 flash attention: reg-P + diagonal specialization ----
// R14 structure; causal-mask ALU now runs only on tiles that can actually
// contain masked elements for this warp (warp-uniform predicate
// k0+63 > q0+wrow). Interior tiles skip 64 cmp/sel per thread.
#define APH 72
#define KVT_H (64 * APH)
#define ATT_SMEM_BYTES ((4 * KVT_H + 128 * APH) * 2)   // 55296 B

__global__ __launch_bounds__(256, 2) void attn_h_kernel(
    const __half* __restrict__ qkv, __half* __restrict__ y)
{
    extern __shared__ __half dsm[];
    __half* Ps = dsm + 4 * KVT_H;            // Q staging only

    const int qb  = gridDim.x - 1 - blockIdx.x;
    const int bh  = blockIdx.y;
    const int b   = bh >> 4;
    const int h   = bh & 15;
    const int tid = threadIdx.x;
    const int wid = tid >> 5;
    const int lane = tid & 31;
    const int gid = lane >> 2;
    const int tig = lane & 3;
    const int wrow = wid * 16;
    const int q0 = qb * 128;

    const __half* base = qkv + (size_t)b * TSEQ * D3;
    const uint32_t smS = smem_u32(dsm);
    const uint32_t psS = smem_u32(Ps);

    const int aRow = lane & 15, aColSel = (lane >> 4) * 8;
    const int bRow = (lane & 7) + ((lane >> 4) << 3);
    const int bColSel = ((lane >> 3) & 1) * 8;
    const int vRow = (lane & 7) + (((lane >> 3) & 1) << 3);
    const int vColSel = (lane >> 4) * 8;

    const int ntiles = (qb + 1) * 2;

    auto load_kv = [&](int t, int s) {
        const int k0 = t * 64;
        uint32_t kS = smS + (uint32_t)(s * 2 * KVT_H) * 2u;
        uint32_t vS = kS + (uint32_t)KVT_H * 2u;
        const __half* kb_ = base + (size_t)k0 * D3 + DMODEL + h * HDIM;
#pragma unroll
        for (int i = 0; i < 2; i++) {
            int idx = tid + i * 256;
            int r = idx >> 3, ch = idx & 7;
            uint32_t off = (uint32_t)(r * APH + ch * 8) * 2u;
            const __half* src = kb_ + (size_t)r * D3 + ch * 8;
            CP_ASYNC16(kS + off, src);
            CP_ASYNC16(vS + off, src + DMODEL);
        }
    };

    load_kv(0, 0); CP_COMMIT();

    {
        const __half2 s = __float2half2_rn(0.125f * 1.44269504089f);
#pragma unroll
        for (int i = 0; i < 4; i++) {
            int idx = tid + i * 256;
            int r = idx >> 3, c8 = (idx & 7) << 3;
            uint4 v = *(const uint4*)(base + (size_t)(q0 + r) * D3 + h * HDIM + c8);
            __half2* h2 = reinterpret_cast<__half2*>(&v);
            h2[0] = __hmul2(h2[0], s); h2[1] = __hmul2(h2[1], s);
            h2[2] = __hmul2(h2[2], s); h2[3] = __hmul2(h2[3], s);
            *(uint4*)&Ps[r * APH + c8] = v;
        }
    }
    __syncthreads();

    uint32_t qf[4][4];
#pragma unroll
    for (int kk = 0; kk < 4; kk++) {
        uint32_t ad = psS + (uint32_t)((wrow + aRow) * APH + kk * 16 + aColSel) * 2u;
        LDSM_X4(qf[kk][0], qf[kk][1], qf[kk][2], qf[kk][3], ad);
    }

    const int r0g = q0 + wrow + gid;
    const int r1g = r0g + 8;

    float m0 = -1e30f, m1 = -1e30f, l0 = 0.f, l1 = 0.f;
    float oacc[8][4];
#pragma unroll
    for (int nt = 0; nt < 8; nt++)
#pragma unroll
        for (int j = 0; j < 4; j++) oacc[nt][j] = 0.f;

    for (int t = 0; t < ntiles; t++) {
        const int k0 = t * 64;
        CP_WAIT0();
        __syncthreads();
        if (t + 1 < ntiles) { load_kv(t + 1, (t + 1) & 1); CP_COMMIT(); }

        if (k0 > q0 + wrow + 15) continue;   // warp fully masked

        const uint32_t kS = smS + (uint32_t)((t & 1) * 2 * KVT_H) * 2u;
        const uint32_t vS = kS + (uint32_t)KVT_H * 2u;

        // ---- S = Q @ K^T (log2 domain) ----
        float sacc[8][4];
#pragma unroll
        for (int nt = 0; nt < 8; nt++)
#pragma unroll
            for (int j = 0; j < 4; j++) sacc[nt][j] = 0.f;
#pragma unroll
        for (int kk = 0; kk < 4; kk++) {
            const int kb = kk * 16;
            uint32_t bf[8][2];
#pragma unroll
            for (int np = 0; np < 4; np++) {
                uint32_t bd = kS + (uint32_t)((np * 16 + bRow) * APH + kb + bColSel) * 2u;
                LDSM_X4(bf[2 * np][0], bf[2 * np][1], bf[2 * np + 1][0], bf[2 * np + 1][1], bd);
            }
#pragma unroll
            for (int nt = 0; nt < 8; nt++)
                MMA_F16(sacc[nt], qf[kk], bf[nt]);
        }

        // ---- causal mask only on diagonal-intersecting tiles (uniform) ----
        if (k0 + 63 > q0 + wrow) {
#pragma unroll
            for (int nt = 0; nt < 8; nt++) {
                int col = k0 + nt * 8 + 2 * tig;
                if (col     > r0g) sacc[nt][0] = -1e30f;
                if (col + 1 > r0g) sacc[nt][1] = -1e30f;
                if (col     > r1g) sacc[nt][2] = -1e30f;
                if (col + 1 > r1g) sacc[nt][3] = -1e30f;
            }
        }

        // ---- quad row max ----
        float tmax0 = -1e30f, tmax1 = -1e30f;
#pragma unroll
        for (int nt = 0; nt < 8; nt++) {
            tmax0 = fmaxf(tmax0, fmaxf(sacc[nt][0], sacc[nt][1]));
            tmax1 = fmaxf(tmax1, fmaxf(sacc[nt][2], sacc[nt][3]));
        }
#pragma unroll
        for (int d = 1; d <= 2; d <<= 1) {
            tmax0 = fmaxf(tmax0, __shfl_xor_sync(0xffffffffu, tmax0, d));
            tmax1 = fmaxf(tmax1, __shfl_xor_sync(0xffffffffu, tmax1, d));
        }

        float mn0 = fmaxf(m0, tmax0), mn1 = fmaxf(m1, tmax1);
        float c0 = exp2f(m0 - mn0), c1 = exp2f(m1 - mn1);
        l0 *= c0; l1 *= c1; m0 = mn0; m1 = mn1;
#pragma unroll
        for (int nt = 0; nt < 8; nt++) {
            oacc[nt][0] *= c0; oacc[nt][1] *= c0;
            oacc[nt][2] *= c1; oacc[nt][3] *= c1;
        }

        // ---- P = 2^(S - m) via ex2.approx.f16x2, kept in registers ----
        uint32_t pp01[8], pp23[8];
#pragma unroll
        for (int nt = 0; nt < 8; nt++) {
            __half2 h01 = __floats2half2_rn(sacc[nt][0] - m0, sacc[nt][1] - m0);
            __half2 h23 = __floats2half2_rn(sacc[nt][2] - m1, sacc[nt][3] - m1);
            __half2 p01 = h2exp2(h01);
            __half2 p23 = h2exp2(h23);
            pp01[nt] = *(uint32_t*)&p01;
            pp23[nt] = *(uint32_t*)&p23;
            l0 += h2sum(p01);
            l1 += h2sum(p23);
        }

        // ---- O += P @ V: A-fragment straight from softmax registers ----
#pragma unroll
        for (int kk = 0; kk < 4; kk++) {
            const int kb = kk * 16;
            uint32_t a[4];
            a[0] = pp01[2 * kk];
            a[1] = pp23[2 * kk];
            a[2] = pp01[2 * kk + 1];
            a[3] = pp23[2 * kk + 1];
            uint32_t bv[8][2];
#pragma unroll
            for (int np = 0; np < 4; np++) {
                uint32_t vd = vS + (uint32_t)((kb + vRow) * APH + np * 16 + vColSel) * 2u;
                LDSM_X4_T(bv[2 * np][0], bv[2 * np][1], bv[2 * np + 1][0], bv[2 * np + 1][1], vd);
            }
#pragma unroll
            for (int nt = 0; nt < 8; nt++)
                MMA_F16(oacc[nt], a, bv[nt]);
        }
    }

    // ---- quad-reduce partial row sums, normalize, store half y ----
#pragma unroll
    for (int d = 1; d <= 2; d <<= 1) {
        l0 += __shfl_xor_sync(0xffffffffu, l0, d);
        l1 += __shfl_xor_sync(0xffffffffu, l1, d);
    }
    float inv0 = 1.f / l0, inv1 = 1.f / l1;
    __half* y0 = y + (size_t)(b * TSEQ + r0g) * DMODEL + h * HDIM;
    __half* y1 = y + (size_t)(b * TSEQ + r1g) * DMODEL + h * HDIM;
#pragma unroll
    for (int nt = 0; nt < 8; nt++) {
        int col = nt * 8 + 2 * tig;
        *(__half2*)(y0 + col) = __floats2half2_rn(oacc[nt][0] * inv0, oacc[nt][1] * inv0);
        *(__half2*)(y1 + col) = __floats2half2_rn(oacc[nt][2] * inv1, oacc[nt][3] * inv1);
    }
}

// ---------------------------------------------------------------------------
extern "C" void kernel_launch(void* const* d_in, const int* in_sizes, int n_in,
                              void* d_out, int out_size)
{
    (void)in_sizes; (void)n_in; (void)out_size;
    const float* x     = (const float*)d_in[0];
    const float* qkv_w = (const float*)d_in[1];
    const float* qkv_b = (const float*)d_in[2];
    const float* o_w   = (const float*)d_in[3];
    const float* o_b   = (const float*)d_in[4];
    float* out = (float*)d_out;

    __half *xh, *qkvh, *yh, *wqkvh, *woh;
    cudaGetSymbolAddress((void**)&xh, g_xh);
    cudaGetSymbolAddress((void**)&qkvh, g_qkvh);
    cudaGetSymbolAddress((void**)&yh, g_yh);
    cudaGetSymbolAddress((void**)&wqkvh, g_wqkvh);
    cudaGetSymbolAddress((void**)&woh, g_woh);

    cudaFuncSetAttribute(gemm_h_kernel<__half>,
                         cudaFuncAttributeMaxDynamicSharedMemorySize, HSMEM_BYTES);
    cudaFuncSetAttribute(gemm_h_kernel<float>,
                         cudaFuncAttributeMaxDynamicSharedMemorySize, HSMEM_BYTES);
    cudaFuncSetAttribute(attn_h_kernel,
                         cudaFuncAttributeMaxDynamicSharedMemorySize, ATT_SMEM_BYTES);

    // prep: single fused fp32 -> fp16 conversion (x, qkv_w, o_w)
    f2h3_kernel<<<1480, 256>>>(x, xh, MROWS * DMODEL / 4,
                               qkv_w, wqkvh, KDIM * D3 / 4,
                               o_w, woh, KDIM * DMODEL / 4);

    // 1) QKV projection
    gemm_h_kernel<__half><<<dim3(D3 / 128, MROWS / 128), 256, HSMEM_BYTES>>>(
        xh, wqkvh, qkv_b, qkvh, D3);

    // 2) causal flash attention
    attn_h_kernel<<<dim3(TSEQ / 128, NBATCH * NHEADS), 256, ATT_SMEM_BYTES>>>(
        qkvh, yh);

    // 3) output projection
    gemm_h_kernel<float><<<dim3(DMODEL / 128, MROWS / 128), 256, HSMEM_BYTES>>>(
        yh, woh, o_b, out, DMODEL);
}

// round 16
// speedup vs baseline: 1.1075x; 1.0238x over previous
#include <cuda_runtime.h>
#include <cuda_fp16.h>
#include <cstdint>
#include <math.h>

#define NBATCH 4
#define TSEQ   2048
#define DMODEL 1024
#define NHEADS 16
#define HDIM   64
#define MROWS  (NBATCH * TSEQ)   // 8192
#define KDIM   DMODEL            // 1024
#define D3     (3 * DMODEL)

// ---------------- scratch (static device globals; no runtime alloc) --------
__device__ __align__(1024) __half g_xh[(size_t)MROWS * DMODEL];        // 16 MB
__device__ __align__(1024) __half g_qkvh[(size_t)MROWS * D3];          // 50 MB
__device__ __align__(1024) __half g_yh[(size_t)MROWS * DMODEL];        // 16 MB
__device__ __align__(1024) __half g_wqkvh[(size_t)KDIM * D3];          // 6 MB
__device__ __align__(1024) __half g_woh[(size_t)KDIM * DMODEL];        // 2 MB

// ---------------- helpers ---------------------------------------------------
#define CP_ASYNC16(dst, src) \
    asm volatile("cp.async.cg.shared.global [%0], [%1], 16;" \
                 :: "r"(dst), "l"(src) : "memory")
#define CP_COMMIT() asm volatile("cp.async.commit_group;" ::: "memory")
#define CP_WAIT1()  asm volatile("cp.async.wait_group 1;" ::: "memory")
#define CP_WAIT0()  asm volatile("cp.async.wait_group 0;" ::: "memory")

__device__ __forceinline__ uint32_t smem_u32(const void* p) {
    uint32_t a;
    asm("{ .reg .u64 t; cvta.to.shared.u64 t, %1; cvt.u32.u64 %0, t; }"
        : "=r"(a) : "l"(p));
    return a;
}

#define MMA_F16(d, a, b) \
    asm volatile("mma.sync.aligned.m16n8k16.row.col.f32.f16.f16.f32 " \
        "{%0,%1,%2,%3}, {%4,%5,%6,%7}, {%8,%9}, {%0,%1,%2,%3};" \
        : "+f"((d)[0]), "+f"((d)[1]), "+f"((d)[2]), "+f"((d)[3]) \
        : "r"((a)[0]), "r"((a)[1]), "r"((a)[2]), "r"((a)[3]), \
          "r"((b)[0]), "r"((b)[1]))

// fp16-accumulator variant: C/D = 2 regs (d01 = row gid pair, d23 = row gid+8)
#define MMA_F16ACC(d01, d23, a, b) \
    asm volatile("mma.sync.aligned.m16n8k16.row.col.f16.f16.f16.f16 " \
        "{%0,%1}, {%2,%3,%4,%5}, {%6,%7}, {%0,%1};" \
        : "+r"(d01), "+r"(d23) \
        : "r"((a)[0]), "r"((a)[1]), "r"((a)[2]), "r"((a)[3]), \
          "r"((b)[0]), "r"((b)[1]))

#define LDSM_X4(r0, r1, r2, r3, addr) \
    asm volatile("ldmatrix.sync.aligned.m8n8.x4.shared.b16 {%0,%1,%2,%3}, [%4];" \
        : "=r"(r0), "=r"(r1), "=r"(r2), "=r"(r3) : "r"(addr))
#define LDSM_X4_T(r0, r1, r2, r3, addr) \
    asm volatile("ldmatrix.sync.aligned.m8n8.x4.trans.shared.b16 {%0,%1,%2,%3}, [%4];" \
        : "=r"(r0), "=r"(r1), "=r"(r2), "=r"(r3) : "r"(addr))

__device__ __forceinline__ void store_pair(float* p, float a, float b) {
    *(float2*)p = make_float2(a, b);
}
__device__ __forceinline__ void store_pair(__half* p, float a, float b) {
    *(__half2*)p = __floats2half2_rn(a, b);
}

__device__ __forceinline__ float h2sum(__half2 v) {
    return __half2float(__hadd(__low2half(v), __high2half(v)));
}

// ---------------- prep: fused fp32 -> fp16 convert (3 segments) ------------
__global__ void f2h3_kernel(const float* __restrict__ in0, __half* __restrict__ out0, int n0,
                            const float* __restrict__ in1, __half* __restrict__ out1, int n1,
                            const float* __restrict__ in2, __half* __restrict__ out2, int n2)
{
    const int ntot = n0 + n1 + n2;
    for (int i = blockIdx.x * blockDim.x + threadIdx.x; i < ntot;
         i += gridDim.x * blockDim.x) {
        const float* in; __half* out; int j = i;
        if (j < n0)            { in = in0; out = out0; }
        else if ((j -= n0) < n1) { in = in1; out = out1; }
        else                   { j -= n1; in = in2; out = out2; }
        float4 v = *(const float4*)(in + (size_t)j * 4);
        __half2 h0 = __floats2half2_rn(v.x, v.y);
        __half2 h1 = __floats2half2_rn(v.z, v.w);
        *(uint2*)(out + (size_t)j * 4) =
            make_uint2(*(uint32_t*)&h0, *(uint32_t*)&h1);
    }
}

// ---------------- fp16 mma GEMM (bias hoist in epilogue) -------------------
#define GBK 64
#define GAP 72
#define GBP 136
#define ATILE_H (128 * GAP)
#define BTILE_H (GBK * GBP)
#define STAGE_H (ATILE_H + BTILE_H)
#define HSMEM_BYTES (3 * STAGE_H * 2)        // 107520 B
#define GCHUNKS (KDIM / GBK)                 // 16

template <typename OutT>
__global__ __launch_bounds__(256, 2) void gemm_h_kernel(
    const __half* __restrict__ A, const __half* __restrict__ W,
    const float* __restrict__ bias, OutT* __restrict__ C, int N)
{
    extern __shared__ __half hsm[];
    const int tid = threadIdx.x;
    const int wid = tid >> 5;
    const int lane = tid & 31;
    const int gid = lane >> 2;
    const int tig = lane & 3;

    const size_t row0 = (size_t)blockIdx.y * 128;
    const size_t col0 = (size_t)blockIdx.x * 128;
    const int wm0 = (wid & 3) * 32;
    const int wn0 = (wid >> 2) * 64;

    const __half* Ab = A + row0 * KDIM;

    float acc[2][8][4];
#pragma unroll
    for (int mt = 0; mt < 2; mt++)
#pragma unroll
        for (int nt = 0; nt < 8; nt++)
#pragma unroll
            for (int j = 0; j < 4; j++) acc[mt][nt][j] = 0.f;

    const uint32_t sbase = smem_u32(hsm);

    const int aRow = lane & 15, aColSel = (lane >> 4) * 8;
    const int tRow = (lane & 7) + (((lane >> 3) & 1) << 3);
    const int tColSel = (lane >> 4) * 8;

    auto load_stage = [&](int s, int chunk) {
        const int kof = chunk * GBK;
        uint32_t aS = sbase + (uint32_t)(s * STAGE_H) * 2u;
        uint32_t bS = aS + (uint32_t)ATILE_H * 2u;
#pragma unroll
        for (int i = 0; i < 4; i++) {
            int idx = tid + i * 256;
            int r = idx >> 3, ch = idx & 7;
            CP_ASYNC16(aS + (uint32_t)(r * GAP + ch * 8) * 2u,
                       Ab + (size_t)r * KDIM + kof + ch * 8);
        }
#pragma unroll
        for (int i = 0; i < 4; i++) {
            int idx = tid + i * 256;
            int r = idx >> 4, ch = idx & 15;
            CP_ASYNC16(bS + (uint32_t)(r * GBP + ch * 8) * 2u,
                       W + (size_t)(kof + r) * N + col0 + ch * 8);
        }
    };

    load_stage(0, 0); CP_COMMIT();
    load_stage(1, 1); CP_COMMIT();

    for (int c = 0; c < GCHUNKS; c++) {
        CP_WAIT1();
        __syncthreads();
        if (c + 2 < GCHUNKS) load_stage((c + 2) % 3, c + 2);
        CP_COMMIT();

        const uint32_t aS = sbase + (uint32_t)((c % 3) * STAGE_H) * 2u;
        const uint32_t bS = aS + (uint32_t)ATILE_H * 2u;
#pragma unroll
        for (int kk = 0; kk < 4; kk++) {
            const int kb = kk * 16;
            uint32_t a[2][4];
#pragma unroll
            for (int mt = 0; mt < 2; mt++) {
                uint32_t ad = aS + (uint32_t)((wm0 + mt * 16 + aRow) * GAP + kb + aColSel) * 2u;
                LDSM_X4(a[mt][0], a[mt][1], a[mt][2], a[mt][3], ad);
            }
            uint32_t b[8][2];
#pragma unroll
            for (int np = 0; np < 4; np++) {
                uint32_t bd = bS + (uint32_t)((kb + tRow) * GBP + wn0 + np * 16 + tColSel) * 2u;
                LDSM_X4_T(b[2 * np][0], b[2 * np][1], b[2 * np + 1][0], b[2 * np + 1][1], bd);
            }
#pragma unroll
            for (int mt = 0; mt < 2; mt++)
#pragma unroll
                for (int nt = 0; nt < 8; nt++)
                    MMA_F16(acc[mt][nt], a[mt], b[nt]);
        }
    }

    // epilogue: bias loaded once per nt (shared across mt)
    float2 bb[8];
#pragma unroll
    for (int nt = 0; nt < 8; nt++)
        bb[nt] = *(const float2*)(bias + col0 + wn0 + nt * 8 + tig * 2);
#pragma unroll
    for (int mt = 0; mt < 2; mt++) {
        size_t r = row0 + wm0 + mt * 16 + gid;
#pragma unroll
        for (int nt = 0; nt < 8; nt++) {
            size_t col = col0 + wn0 + nt * 8 + tig * 2;
            store_pair(C + r * N + col, acc[mt][nt][0] + bb[nt].x, acc[mt][nt][1] + bb[nt].y);
            store_pair(C + (r + 8) * N + col, acc[mt][nt][2] + bb[nt].x, acc[mt][nt][3] + bb[nt].y);
        }
    }
}

// ---------------- fp16 flash attention: f16-accum S-phase ------------------
// S = Q@K^T now uses the fp16-accumulator HMMA (2x rate, half the C regs);
// its C-fragment (s01/s23 half2 pairs) doubles as the PV A-fragment after
// in-place exp2. Masking with half -inf on diagonal tiles only. PV stays
// fp32-acc. Register-resident P (R14), 2-stage cp.async K/V (R10).
#define APH 72
#define KVT_H (64 * APH)
#define ATT_SMEM_BYTES ((4 * KVT_H + 128 * APH) * 2)   // 55296 B

__global__ __launch_bounds__(256, 2) void attn_h_kernel(
    const __half* __restrict__ qkv, __half* __restrict__ y)
{
    extern __shared__ __half dsm[];
    __half* Ps = dsm + 4 * KVT_H;            // Q staging only

    const int qb  = gridDim.x - 1 - blockIdx.x;
    const int bh  = blockIdx.y;
    const int b   = bh >> 4;
    const int h   = bh & 15;
    const int tid = threadIdx.x;
    const int wid = tid >> 5;
    const int lane = tid & 31;
    const int gid = lane >> 2;
    const int tig = lane & 3;
    const int wrow = wid * 16;
    const int q0 = qb * 128;

    const __half* base = qkv + (size_t)b * TSEQ * D3;
    const uint32_t smS = smem_u32(dsm);
    const uint32_t psS = smem_u32(Ps);

    const int aRow = lane & 15, aColSel = (lane >> 4) * 8;
    const int bRow = (lane & 7) + ((lane >> 4) << 3);
    const int bColSel = ((lane >> 3) & 1) * 8;
    const int vRow = (lane & 7) + (((lane >> 3) & 1) << 3);
    const int vColSel = (lane >> 4) * 8;

    const int ntiles = (qb + 1) * 2;
    const __half HNEG = __ushort_as_half((unsigned short)0xFC00);  // -inf

    auto load_kv = [&](int t, int s) {
        const int k0 = t * 64;
        uint32_t kS = smS + (uint32_t)(s * 2 * KVT_H) * 2u;
        uint32_t vS = kS + (uint32_t)KVT_H * 2u;
        const __half* kb_ = base + (size_t)k0 * D3 + DMODEL + h * HDIM;
#pragma unroll
        for (int i = 0; i < 2; i++) {
            int idx = tid + i * 256;
            int r = idx >> 3, ch = idx & 7;
            uint32_t off = (uint32_t)(r * APH + ch * 8) * 2u;
            const __half* src = kb_ + (size_t)r * D3 + ch * 8;
            CP_ASYNC16(kS + off, src);
            CP_ASYNC16(vS + off, src + DMODEL);
        }
    };

    load_kv(0, 0); CP_COMMIT();

    {
        const __half2 s = __float2half2_rn(0.125f * 1.44269504089f);
#pragma unroll
        for (int i = 0; i < 4; i++) {
            int idx = tid + i * 256;
            int r = idx >> 3, c8 = (idx & 7) << 3;
            uint4 v = *(const uint4*)(base + (size_t)(q0 + r) * D3 + h * HDIM + c8);
            __half2* h2 = reinterpret_cast<__half2*>(&v);
            h2[0] = __hmul2(h2[0], s); h2[1] = __hmul2(h2[1], s);
            h2[2] = __hmul2(h2[2], s); h2[3] = __hmul2(h2[3], s);
            *(uint4*)&Ps[r * APH + c8] = v;
        }
    }
    __syncthreads();

    uint32_t qf[4][4];
#pragma unroll
    for (int kk = 0; kk < 4; kk++) {
        uint32_t ad = psS + (uint32_t)((wrow + aRow) * APH + kk * 16 + aColSel) * 2u;
        LDSM_X4(qf[kk][0], qf[kk][1], qf[kk][2], qf[kk][3], ad);
    }

    const int r0g = q0 + wrow + gid;
    const int r1g = r0g + 8;

    float m0 = -1e30f, m1 = -1e30f, l0 = 0.f, l1 = 0.f;
    float oacc[8][4];
#pragma unroll
    for (int nt = 0; nt < 8; nt++)
#pragma unroll
        for (int j = 0; j < 4; j++) oacc[nt][j] = 0.f;

    for (int t = 0; t < ntiles; t++) {
        const int k0 = t * 64;
        CP_WAIT0();
        __syncthreads();
        if (t + 1 < ntiles) { load_kv(t + 1, (t + 1) & 1); CP_COMMIT(); }

        if (k0 > q0 + wrow + 15) continue;   // warp fully masked

        const uint32_t kS = smS + (uint32_t)((t & 1) * 2 * KVT_H) * 2u;
        const uint32_t vS = kS + (uint32_t)KVT_H * 2u;

        // ---- S = Q @ K^T (log2 domain, fp16 accumulators) ----
        uint32_t s01[8], s23[8];
#pragma unroll
        for (int nt = 0; nt < 8; nt++) { s01[nt] = 0u; s23[nt] = 0u; }
#pragma unroll
        for (int kk = 0; kk < 4; kk++) {
            const int kb = kk * 16;
            uint32_t bf[8][2];
#pragma unroll
            for (int np = 0; np < 4; np++) {
                uint32_t bd = kS + (uint32_t)((np * 16 + bRow) * APH + kb + bColSel) * 2u;
                LDSM_X4(bf[2 * np][0], bf[2 * np][1], bf[2 * np + 1][0], bf[2 * np + 1][1], bd);
            }
#pragma unroll
            for (int nt = 0; nt < 8; nt++)
                MMA_F16ACC(s01[nt], s23[nt], qf[kk], bf[nt]);
        }

        // ---- causal mask (half -inf) on diagonal tiles only ----
        if (k0 + 63 > q0 + wrow) {
#pragma unroll
            for (int nt = 0; nt < 8; nt++) {
                int col = k0 + nt * 8 + 2 * tig;
                __half2 v01 = *(__half2*)&s01[nt];
                __half2 v23 = *(__half2*)&s23[nt];
                if (col     > r0g) v01 = __halves2half2(HNEG, __high2half(v01));
                if (col + 1 > r0g) v01 = __halves2half2(__low2half(v01), HNEG);
                if (col     > r1g) v23 = __halves2half2(HNEG, __high2half(v23));
                if (col + 1 > r1g) v23 = __halves2half2(__low2half(v23), HNEG);
                s01[nt] = *(uint32_t*)&v01;
                s23[nt] = *(uint32_t*)&v23;
            }
        }

        // ---- quad row max (hmax2 tree then cross-quad shuffles) ----
        __half2 mx0 = *(__half2*)&s01[0];
        __half2 mx1 = *(__half2*)&s23[0];
#pragma unroll
        for (int nt = 1; nt < 8; nt++) {
            mx0 = __hmax2(mx0, *(__half2*)&s01[nt]);
            mx1 = __hmax2(mx1, *(__half2*)&s23[nt]);
        }
        float tmax0 = fmaxf(__half2float(__low2half(mx0)), __half2float(__high2half(mx0)));
        float tmax1 = fmaxf(__half2float(__low2half(mx1)), __half2float(__high2half(mx1)));
#pragma unroll
        for (int d = 1; d <= 2; d <<= 1) {
            tmax0 = fmaxf(tmax0, __shfl_xor_sync(0xffffffffu, tmax0, d));
            tmax1 = fmaxf(tmax1, __shfl_xor_sync(0xffffffffu, tmax1, d));
        }

        float mn0 = fmaxf(m0, tmax0), mn1 = fmaxf(m1, tmax1);
        float c0 = exp2f(m0 - mn0), c1 = exp2f(m1 - mn1);
        l0 *= c0; l1 *= c1; m0 = mn0; m1 = mn1;
#pragma unroll
        for (int nt = 0; nt < 8; nt++) {
            oacc[nt][0] *= c0; oacc[nt][1] *= c0;
            oacc[nt][2] *= c1; oacc[nt][3] *= c1;
        }

        // ---- P = 2^(S - m) in place (HSUB2 + ex2.f16x2); accumulate l ----
        const __half2 mh0 = __float2half2_rn(m0);
        const __half2 mh1 = __float2half2_rn(m1);
#pragma unroll
        for (int nt = 0; nt < 8; nt++) {
            __half2 p01 = h2exp2(__hsub2(*(__half2*)&s01[nt], mh0));
            __half2 p23 = h2exp2(__hsub2(*(__half2*)&s23[nt], mh1));
            s01[nt] = *(uint32_t*)&p01;
            s23[nt] = *(uint32_t*)&p23;
            l0 += h2sum(p01);
            l1 += h2sum(p23);
        }

        // ---- O += P @ V: A-fragment = S C-fragment directly ----
#pragma unroll
        for (int kk = 0; kk < 4; kk++) {
            const int kb = kk * 16;
            uint32_t a[4];
            a[0] = s01[2 * kk];
            a[1] = s23[2 * kk];
            a[2] = s01[2 * kk + 1];
            a[3] = s23[2 * kk + 1];
            uint32_t bv[8][2];
#pragma unroll
            for (int np = 0; np < 4; np++) {
                uint32_t vd = vS + (uint32_t)((kb + vRow) * APH + np * 16 + vColSel) * 2u;
                LDSM_X4_T(bv[2 * np][0], bv[2 * np][1], bv[2 * np + 1][0], bv[2 * np + 1][1], vd);
            }
#pragma unroll
            for (int nt = 0; nt < 8; nt++)
                MMA_F16(oacc[nt], a, bv[nt]);
        }
    }

    // ---- quad-reduce partial row sums, normalize, store half y ----
#pragma unroll
    for (int d = 1; d <= 2; d <<= 1) {
        l0 += __shfl_xor_sync(0xffffffffu, l0, d);
        l1 += __shfl_xor_sync(0xffffffffu, l1, d);
    }
    float inv0 = 1.f / l0, inv1 = 1.f / l1;
    __half* y0 = y + (size_t)(b * TSEQ + r0g) * DMODEL + h * HDIM;
    __half* y1 = y + (size_t)(b * TSEQ + r1g) * DMODEL + h * HDIM;
#pragma unroll
    for (int nt = 0; nt < 8; nt++) {
        int col = nt * 8 + 2 * tig;
        *(__half2*)(y0 + col) = __floats2half2_rn(oacc[nt][0] * inv0, oacc[nt][1] * inv0);
        *(__half2*)(y1 + col) = __floats2half2_rn(oacc[nt][2] * inv1, oacc[nt][3] * inv1);
    }
}

// ---------------------------------------------------------------------------
extern "C" void kernel_launch(void* const* d_in, const int* in_sizes, int n_in,
                              void* d_out, int out_size)
{
    (void)in_sizes; (void)n_in; (void)out_size;
    const float* x     = (const float*)d_in[0];
    const float* qkv_w = (const float*)d_in[1];
    const float* qkv_b = (const float*)d_in[2];
    const float* o_w   = (const float*)d_in[3];
    const float* o_b   = (const float*)d_in[4];
    float* out = (float*)d_out;

    __half *xh, *qkvh, *yh, *wqkvh, *woh;
    cudaGetSymbolAddress((void**)&xh, g_xh);
    cudaGetSymbolAddress((void**)&qkvh, g_qkvh);
    cudaGetSymbolAddress((void**)&yh, g_yh);
    cudaGetSymbolAddress((void**)&wqkvh, g_wqkvh);
    cudaGetSymbolAddress((void**)&woh, g_woh);

    cudaFuncSetAttribute(gemm_h_kernel<__half>,
                         cudaFuncAttributeMaxDynamicSharedMemorySize, HSMEM_BYTES);
    cudaFuncSetAttribute(gemm_h_kernel<float>,
                         cudaFuncAttributeMaxDynamicSharedMemorySize, HSMEM_BYTES);
    cudaFuncSetAttribute(attn_h_kernel,
                         cudaFuncAttributeMaxDynamicSharedMemorySize, ATT_SMEM_BYTES);

    // prep: single fused fp32 -> fp16 conversion (x, qkv_w, o_w)
    f2h3_kernel<<<1480, 256>>>(x, xh, MROWS * DMODEL / 4,
                               qkv_w, wqkvh, KDIM * D3 / 4,
                               o_w, woh, KDIM * DMODEL / 4);

    // 1) QKV projection
    gemm_h_kernel<__half><<<dim3(D3 / 128, MROWS / 128), 256, HSMEM_BYTES>>>(
        xh, wqkvh, qkv_b, qkvh, D3);

    // 2) causal flash attention
    attn_h_kernel<<<dim3(TSEQ / 128, NBATCH * NHEADS), 256, ATT_SMEM_BYTES>>>(
        qkvh, yh);

    // 3) output projection
    gemm_h_kernel<float><<<dim3(DMODEL / 128, MROWS / 128), 256, HSMEM_BYTES>>>(
        yh, woh, o_b, out, DMODEL);
}

// round 17
// speedup vs baseline: 1.1092x; 1.0015x over previous
#include <cuda_runtime.h>
#include <cuda_fp16.h>
#include <cstdint>
#include <math.h>

#define NBATCH 4
#define TSEQ   2048
#define DMODEL 1024
#define NHEADS 16
#define HDIM   64
#define MROWS  (NBATCH * TSEQ)   // 8192
#define KDIM   DMODEL            // 1024
#define D3     (3 * DMODEL)

// ---------------- scratch (static device globals; no runtime alloc) --------
__device__ __align__(1024) __half g_xh[(size_t)MROWS * DMODEL];        // 16 MB
__device__ __align__(1024) __half g_qkvh[(size_t)MROWS * D3];          // 50 MB
__device__ __align__(1024) __half g_yh[(size_t)MROWS * DMODEL];        // 16 MB
__device__ __align__(1024) __half g_wqkvh[(size_t)KDIM * D3];          // 6 MB
__device__ __align__(1024) __half g_woh[(size_t)KDIM * DMODEL];        // 2 MB

// ---------------- helpers ---------------------------------------------------
#define CP_ASYNC16(dst, src) \
    asm volatile("cp.async.cg.shared.global [%0], [%1], 16;" \
                 :: "r"(dst), "l"(src) : "memory")
#define CP_COMMIT() asm volatile("cp.async.commit_group;" ::: "memory")
#define CP_WAIT1()  asm volatile("cp.async.wait_group 1;" ::: "memory")
#define CP_WAIT0()  asm volatile("cp.async.wait_group 0;" ::: "memory")

__device__ __forceinline__ uint32_t smem_u32(const void* p) {
    uint32_t a;
    asm("{ .reg .u64 t; cvta.to.shared.u64 t, %1; cvt.u32.u64 %0, t; }"
        : "=r"(a) : "l"(p));
    return a;
}

#define MMA_F16(d, a, b) \
    asm volatile("mma.sync.aligned.m16n8k16.row.col.f32.f16.f16.f32 " \
        "{%0,%1,%2,%3}, {%4,%5,%6,%7}, {%8,%9}, {%0,%1,%2,%3};" \
        : "+f"((d)[0]), "+f"((d)[1]), "+f"((d)[2]), "+f"((d)[3]) \
        : "r"((a)[0]), "r"((a)[1]), "r"((a)[2]), "r"((a)[3]), \
          "r"((b)[0]), "r"((b)[1]))

// fp16-accumulator variant: C/D = 2 regs (d01 = row gid pair, d23 = row gid+8)
#define MMA_F16ACC(d01, d23, a, b) \
    asm volatile("mma.sync.aligned.m16n8k16.row.col.f16.f16.f16.f16 " \
        "{%0,%1}, {%2,%3,%4,%5}, {%6,%7}, {%0,%1};" \
        : "+r"(d01), "+r"(d23) \
        : "r"((a)[0]), "r"((a)[1]), "r"((a)[2]), "r"((a)[3]), \
          "r"((b)[0]), "r"((b)[1]))

#define LDSM_X4(r0, r1, r2, r3, addr) \
    asm volatile("ldmatrix.sync.aligned.m8n8.x4.shared.b16 {%0,%1,%2,%3}, [%4];" \
        : "=r"(r0), "=r"(r1), "=r"(r2), "=r"(r3) : "r"(addr))
#define LDSM_X4_T(r0, r1, r2, r3, addr) \
    asm volatile("ldmatrix.sync.aligned.m8n8.x4.trans.shared.b16 {%0,%1,%2,%3}, [%4];" \
        : "=r"(r0), "=r"(r1), "=r"(r2), "=r"(r3) : "r"(addr))

__device__ __forceinline__ void store_pair(float* p, float a, float b) {
    *(float2*)p = make_float2(a, b);
}
__device__ __forceinline__ void store_pair(__half* p, float a, float b) {
    *(__half2*)p = __floats2half2_rn(a, b);
}

__device__ __forceinline__ float h2sum(__half2 v) {
    return __half2float(__hadd(__low2half(v), __high2half(v)));
}

// ---------------- prep: fused fp32 -> fp16 convert (3 segments) ------------
__global__ void f2h3_kernel(const float* __restrict__ in0, __half* __restrict__ out0, int n0,
                            const float* __restrict__ in1, __half* __restrict__ out1, int n1,
                            const float* __restrict__ in2, __half* __restrict__ out2, int n2)
{
    const int ntot = n0 + n1 + n2;
    for (int i = blockIdx.x * blockDim.x + threadIdx.x; i < ntot;
         i += gridDim.x * blockDim.x) {
        const float* in; __half* out; int j = i;
        if (j < n0)            { in = in0; out = out0; }
        else if ((j -= n0) < n1) { in = in1; out = out1; }
        else                   { j -= n1; in = in2; out = out2; }
        float4 v = *(const float4*)(in + (size_t)j * 4);
        __half2 h0 = __floats2half2_rn(v.x, v.y);
        __half2 h1 = __floats2half2_rn(v.z, v.w);
        *(uint2*)(out + (size_t)j * 4) =
            make_uint2(*(uint32_t*)&h0, *(uint32_t*)&h1);
    }
}

// ---------------- fp16 mma GEMM (split B-fragment halves) ------------------
#define GBK 64
#define GAP 72
#define GBP 136
#define ATILE_H (128 * GAP)
#define BTILE_H (GBK * GBP)
#define STAGE_H (ATILE_H + BTILE_H)
#define HSMEM_BYTES (3 * STAGE_H * 2)        // 107520 B
#define GCHUNKS (KDIM / GBK)                 // 16

template <typename OutT>
__global__ __launch_bounds__(256, 2) void gemm_h_kernel(
    const __half* __restrict__ A, const __half* __restrict__ W,
    const float* __restrict__ bias, OutT* __restrict__ C, int N)
{
    extern __shared__ __half hsm[];
    const int tid = threadIdx.x;
    const int wid = tid >> 5;
    const int lane = tid & 31;
    const int gid = lane >> 2;
    const int tig = lane & 3;

    const size_t row0 = (size_t)blockIdx.y * 128;
    const size_t col0 = (size_t)blockIdx.x * 128;
    const int wm0 = (wid & 3) * 32;
    const int wn0 = (wid >> 2) * 64;

    const __half* Ab = A + row0 * KDIM;

    float acc[2][8][4];
#pragma unroll
    for (int mt = 0; mt < 2; mt++)
#pragma unroll
        for (int nt = 0; nt < 8; nt++)
#pragma unroll
            for (int j = 0; j < 4; j++) acc[mt][nt][j] = 0.f;

    const uint32_t sbase = smem_u32(hsm);

    const int aRow = lane & 15, aColSel = (lane >> 4) * 8;
    const int tRow = (lane & 7) + (((lane >> 3) & 1) << 3);
    const int tColSel = (lane >> 4) * 8;

    auto load_stage = [&](int s, int chunk) {
        const int kof = chunk * GBK;
        uint32_t aS = sbase + (uint32_t)(s * STAGE_H) * 2u;
        uint32_t bS = aS + (uint32_t)ATILE_H * 2u;
#pragma unroll
        for (int i = 0; i < 4; i++) {
            int idx = tid + i * 256;
            int r = idx >> 3, ch = idx & 7;
            CP_ASYNC16(aS + (uint32_t)(r * GAP + ch * 8) * 2u,
                       Ab + (size_t)r * KDIM + kof + ch * 8);
        }
#pragma unroll
        for (int i = 0; i < 4; i++) {
            int idx = tid + i * 256;
            int r = idx >> 4, ch = idx & 15;
            CP_ASYNC16(bS + (uint32_t)(r * GBP + ch * 8) * 2u,
                       W + (size_t)(kof + r) * N + col0 + ch * 8);
        }
    };

    load_stage(0, 0); CP_COMMIT();
    load_stage(1, 1); CP_COMMIT();

    for (int c = 0; c < GCHUNKS; c++) {
        CP_WAIT1();
        __syncthreads();
        if (c + 2 < GCHUNKS) load_stage((c + 2) % 3, c + 2);
        CP_COMMIT();

        const uint32_t aS = sbase + (uint32_t)((c % 3) * STAGE_H) * 2u;
        const uint32_t bS = aS + (uint32_t)ATILE_H * 2u;
#pragma unroll
        for (int kk = 0; kk < 4; kk++) {
            const int kb = kk * 16;
            uint32_t a[2][4];
#pragma unroll
            for (int mt = 0; mt < 2; mt++) {
                uint32_t ad = aS + (uint32_t)((wm0 + mt * 16 + aRow) * GAP + kb + aColSel) * 2u;
                LDSM_X4(a[mt][0], a[mt][1], a[mt][2], a[mt][3], ad);
            }
            // half 1: B frags for nt 0..3
            uint32_t b[4][2];
#pragma unroll
            for (int np = 0; np < 2; np++) {
                uint32_t bd = bS + (uint32_t)((kb + tRow) * GBP + wn0 + np * 16 + tColSel) * 2u;
                LDSM_X4_T(b[2 * np][0], b[2 * np][1], b[2 * np + 1][0], b[2 * np + 1][1], bd);
            }
#pragma unroll
            for (int mt = 0; mt < 2; mt++)
#pragma unroll
                for (int nt = 0; nt < 4; nt++)
                    MMA_F16(acc[mt][nt], a[mt], b[nt]);
            // half 2: B frags for nt 4..7
#pragma unroll
            for (int np = 0; np < 2; np++) {
                uint32_t bd = bS + (uint32_t)((kb + tRow) * GBP + wn0 + (np + 2) * 16 + tColSel) * 2u;
                LDSM_X4_T(b[2 * np][0], b[2 * np][1], b[2 * np + 1][0], b[2 * np + 1][1], bd);
            }
#pragma unroll
            for (int mt = 0; mt < 2; mt++)
#pragma unroll
                for (int nt = 0; nt < 4; nt++)
                    MMA_F16(acc[mt][nt + 4], a[mt], b[nt]);
        }
    }

    // epilogue: bias loaded once per nt (shared across mt)
    float2 bb[8];
#pragma unroll
    for (int nt = 0; nt < 8; nt++)
        bb[nt] = *(const float2*)(bias + col0 + wn0 + nt * 8 + tig * 2);
#pragma unroll
    for (int mt = 0; mt < 2; mt++) {
        size_t r = row0 + wm0 + mt * 16 + gid;
#pragma unroll
        for (int nt = 0; nt < 8; nt++) {
            size_t col = col0 + wn0 + nt * 8 + tig * 2;
            store_pair(C + r * N + col, acc[mt][nt][0] + bb[nt].x, acc[mt][nt][1] + bb[nt].y);
            store_pair(C + (r + 8) * N + col, acc[mt][nt][2] + bb[nt].x, acc[mt][nt][3] + bb[nt].y);
        }
    }
}

// ---------------- fp16 flash attention: 128-key tiles ----------------------
// ABN=128: half the tile-loop barriers per key vs R16. f16-acc S-phase whose
// C-fragment doubles as the PV A-fragment; register-resident P; 2-stage
// cp.async K/V; log2-domain f16x2 softmax. SMEM 92160 B -> 2 CTAs/SM.
#define ABN 128
#define APH 72
#define KVT_H (ABN * APH)                              // 9216 halves
#define ATT_SMEM_BYTES ((4 * KVT_H + 128 * APH) * 2)   // 92160 B

__global__ __launch_bounds__(256, 2) void attn_h_kernel(
    const __half* __restrict__ qkv, __half* __restrict__ y)
{
    extern __shared__ __half dsm[];
    __half* Ps = dsm + 4 * KVT_H;            // Q staging only

    const int qb  = gridDim.x - 1 - blockIdx.x;
    const int bh  = blockIdx.y;
    const int b   = bh >> 4;
    const int h   = bh & 15;
    const int tid = threadIdx.x;
    const int wid = tid >> 5;
    const int lane = tid & 31;
    const int gid = lane >> 2;
    const int tig = lane & 3;
    const int wrow = wid * 16;
    const int q0 = qb * 128;

    const __half* base = qkv + (size_t)b * TSEQ * D3;
    const uint32_t smS = smem_u32(dsm);
    const uint32_t psS = smem_u32(Ps);

    const int aRow = lane & 15, aColSel = (lane >> 4) * 8;
    const int bRow = (lane & 7) + ((lane >> 4) << 3);
    const int bColSel = ((lane >> 3) & 1) * 8;
    const int vRow = (lane & 7) + (((lane >> 3) & 1) << 3);
    const int vColSel = (lane >> 4) * 8;

    const int ntiles = qb + 1;                         // 128-key tiles
    const __half HNEG = __ushort_as_half((unsigned short)0xFC00);  // -inf

    auto load_kv = [&](int t, int s) {
        const int k0 = t * ABN;
        uint32_t kS = smS + (uint32_t)(s * 2 * KVT_H) * 2u;
        uint32_t vS = kS + (uint32_t)KVT_H * 2u;
        const __half* kb_ = base + (size_t)k0 * D3 + DMODEL + h * HDIM;
#pragma unroll
        for (int i = 0; i < 4; i++) {                  // 128 rows x 64 halves
            int idx = tid + i * 256;
            int r = idx >> 3, ch = idx & 7;
            uint32_t off = (uint32_t)(r * APH + ch * 8) * 2u;
            const __half* src = kb_ + (size_t)r * D3 + ch * 8;
            CP_ASYNC16(kS + off, src);
            CP_ASYNC16(vS + off, src + DMODEL);
        }
    };

    load_kv(0, 0); CP_COMMIT();

    {
        const __half2 s = __float2half2_rn(0.125f * 1.44269504089f);
#pragma unroll
        for (int i = 0; i < 4; i++) {
            int idx = tid + i * 256;
            int r = idx >> 3, c8 = (idx & 7) << 3;
            uint4 v = *(const uint4*)(base + (size_t)(q0 + r) * D3 + h * HDIM + c8);
            __half2* h2 = reinterpret_cast<__half2*>(&v);
            h2[0] = __hmul2(h2[0], s); h2[1] = __hmul2(h2[1], s);
            h2[2] = __hmul2(h2[2], s); h2[3] = __hmul2(h2[3], s);
            *(uint4*)&Ps[r * APH + c8] = v;
        }
    }
    __syncthreads();

    uint32_t qf[4][4];
#pragma unroll
    for (int kk = 0; kk < 4; kk++) {
        uint32_t ad = psS + (uint32_t)((wrow + aRow) * APH + kk * 16 + aColSel) * 2u;
        LDSM_X4(qf[kk][0], qf[kk][1], qf[kk][2], qf[kk][3], ad);
    }

    const int r0g = q0 + wrow + gid;
    const int r1g = r0g + 8;

    float m0 = -1e30f, m1 = -1e30f, l0 = 0.f, l1 = 0.f;
    float oacc[8][4];
#pragma unroll
    for (int nt = 0; nt < 8; nt++)
#pragma unroll
        for (int j = 0; j < 4; j++) oacc[nt][j] = 0.f;

    for (int t = 0; t < ntiles; t++) {
        const int k0 = t * ABN;
        CP_WAIT0();
        __syncthreads();
        if (t + 1 < ntiles) { load_kv(t + 1, (t + 1) & 1); CP_COMMIT(); }

        const uint32_t kS = smS + (uint32_t)((t & 1) * 2 * KVT_H) * 2u;
        const uint32_t vS = kS + (uint32_t)KVT_H * 2u;

        // ---- S = Q @ K^T (log2 domain, fp16 accumulators, 128 cols) ----
        uint32_t s01[16], s23[16];
#pragma unroll
        for (int nt = 0; nt < 16; nt++) { s01[nt] = 0u; s23[nt] = 0u; }
#pragma unroll
        for (int kk = 0; kk < 4; kk++) {
            const int kb = kk * 16;
            uint32_t bf[8][2];
            // half 1: key cols 0..63 (nt 0..7)
#pragma unroll
            for (int np = 0; np < 4; np++) {
                uint32_t bd = kS + (uint32_t)((np * 16 + bRow) * APH + kb + bColSel) * 2u;
                LDSM_X4(bf[2 * np][0], bf[2 * np][1], bf[2 * np + 1][0], bf[2 * np + 1][1], bd);
            }
#pragma unroll
            for (int nt = 0; nt < 8; nt++)
                MMA_F16ACC(s01[nt], s23[nt], qf[kk], bf[nt]);
            // half 2: key cols 64..127 (nt 8..15)
#pragma unroll
            for (int np = 0; np < 4; np++) {
                uint32_t bd = kS + (uint32_t)(((np + 4) * 16 + bRow) * APH + kb + bColSel) * 2u;
                LDSM_X4(bf[2 * np][0], bf[2 * np][1], bf[2 * np + 1][0], bf[2 * np + 1][1], bd);
            }
#pragma unroll
            for (int nt = 0; nt < 8; nt++)
                MMA_F16ACC(s01[nt + 8], s23[nt + 8], qf[kk], bf[nt]);
        }

        // ---- causal mask (half -inf) on the diagonal tile only ----
        if (k0 + ABN - 1 > q0 + wrow) {
#pragma unroll
            for (int nt = 0; nt < 16; nt++) {
                int col = k0 + nt * 8 + 2 * tig;
                __half2 v01 = *(__half2*)&s01[nt];
                __half2 v23 = *(__half2*)&s23[nt];
                if (col     > r0g) v01 = __halves2half2(HNEG, __high2half(v01));
                if (col + 1 > r0g) v01 = __halves2half2(__low2half(v01), HNEG);
                if (col     > r1g) v23 = __halves2half2(HNEG, __high2half(v23));
                if (col + 1 > r1g) v23 = __halves2half2(__low2half(v23), HNEG);
                s01[nt] = *(uint32_t*)&v01;
                s23[nt] = *(uint32_t*)&v23;
            }
        }

        // ---- quad row max ----
        __half2 mx0 = *(__half2*)&s01[0];
        __half2 mx1 = *(__half2*)&s23[0];
#pragma unroll
        for (int nt = 1; nt < 16; nt++) {
            mx0 = __hmax2(mx0, *(__half2*)&s01[nt]);
            mx1 = __hmax2(mx1, *(__half2*)&s23[nt]);
        }
        float tmax0 = fmaxf(__half2float(__low2half(mx0)), __half2float(__high2half(mx0)));
        float tmax1 = fmaxf(__half2float(__low2half(mx1)), __half2float(__high2half(mx1)));
#pragma unroll
        for (int d = 1; d <= 2; d <<= 1) {
            tmax0 = fmaxf(tmax0, __shfl_xor_sync(0xffffffffu, tmax0, d));
            tmax1 = fmaxf(tmax1, __shfl_xor_sync(0xffffffffu, tmax1, d));
        }

        float mn0 = fmaxf(m0, tmax0), mn1 = fmaxf(m1, tmax1);
        float c0 = exp2f(m0 - mn0), c1 = exp2f(m1 - mn1);
        l0 *= c0; l1 *= c1; m0 = mn0; m1 = mn1;
#pragma unroll
        for (int nt = 0; nt < 8; nt++) {
            oacc[nt][0] *= c0; oacc[nt][1] *= c0;
            oacc[nt][2] *= c1; oacc[nt][3] *= c1;
        }

        // ---- P = 2^(S - m) in place; accumulate l ----
        const __half2 mh0 = __float2half2_rn(m0);
        const __half2 mh1 = __float2half2_rn(m1);
#pragma unroll
        for (int nt = 0; nt < 16; nt++) {
            __half2 p01 = h2exp2(__hsub2(*(__half2*)&s01[nt], mh0));
            __half2 p23 = h2exp2(__hsub2(*(__half2*)&s23[nt], mh1));
            s01[nt] = *(uint32_t*)&p01;
            s23[nt] = *(uint32_t*)&p23;
            l0 += h2sum(p01);
            l1 += h2sum(p23);
        }

        // ---- O += P @ V: A-fragment = S C-fragment, 8 k-groups ----
#pragma unroll
        for (int kk = 0; kk < 8; kk++) {
            const int kb = kk * 16;
            uint32_t a[4];
            a[0] = s01[2 * kk];
            a[1] = s23[2 * kk];
            a[2] = s01[2 * kk + 1];
            a[3] = s23[2 * kk + 1];
            uint32_t bv[8][2];
#pragma unroll
            for (int np = 0; np < 4; np++) {
                uint32_t vd = vS + (uint32_t)((kb + vRow) * APH + np * 16 + vColSel) * 2u;
                LDSM_X4_T(bv[2 * np][0], bv[2 * np][1], bv[2 * np + 1][0], bv[2 * np + 1][1], vd);
            }
#pragma unroll
            for (int nt = 0; nt < 8; nt++)
                MMA_F16(oacc[nt], a, bv[nt]);
        }
    }

    // ---- quad-reduce partial row sums, normalize, store half y ----
#pragma unroll
    for (int d = 1; d <= 2; d <<= 1) {
        l0 += __shfl_xor_sync(0xffffffffu, l0, d);
        l1 += __shfl_xor_sync(0xffffffffu, l1, d);
    }
    float inv0 = 1.f / l0, inv1 = 1.f / l1;
    __half* y0 = y + (size_t)(b * TSEQ + r0g) * DMODEL + h * HDIM;
    __half* y1 = y + (size_t)(b * TSEQ + r1g) * DMODEL + h * HDIM;
#pragma unroll
    for (int nt = 0; nt < 8; nt++) {
        int col = nt * 8 + 2 * tig;
        *(__half2*)(y0 + col) = __floats2half2_rn(oacc[nt][0] * inv0, oacc[nt][1] * inv0);
        *(__half2*)(y1 + col) = __floats2half2_rn(oacc[nt][2] * inv1, oacc[nt][3] * inv1);
    }
}

// ---------------------------------------------------------------------------
extern "C" void kernel_launch(void* const* d_in, const int* in_sizes, int n_in,
                              void* d_out, int out_size)
{
    (void)in_sizes; (void)n_in; (void)out_size;
    const float* x     = (const float*)d_in[0];
    const float* qkv_w = (const float*)d_in[1];
    const float* qkv_b = (const float*)d_in[2];
    const float* o_w   = (const float*)d_in[3];
    const float* o_b   = (const float*)d_in[4];
    float* out = (float*)d_out;

    __half *xh, *qkvh, *yh, *wqkvh, *woh;
    cudaGetSymbolAddress((void**)&xh, g_xh);
    cudaGetSymbolAddress((void**)&qkvh, g_qkvh);
    cudaGetSymbolAddress((void**)&yh, g_yh);
    cudaGetSymbolAddress((void**)&wqkvh, g_wqkvh);
    cudaGetSymbolAddress((void**)&woh, g_woh);

    cudaFuncSetAttribute(gemm_h_kernel<__half>,
                         cudaFuncAttributeMaxDynamicSharedMemorySize, HSMEM_BYTES);
    cudaFuncSetAttribute(gemm_h_kernel<float>,
                         cudaFuncAttributeMaxDynamicSharedMemorySize, HSMEM_BYTES);
    cudaFuncSetAttribute(attn_h_kernel,
                         cudaFuncAttributeMaxDynamicSharedMemorySize, ATT_SMEM_BYTES);

    // prep: single fused fp32 -> fp16 conversion (x, qkv_w, o_w)
    f2h3_kernel<<<1480, 256>>>(x, xh, MROWS * DMODEL / 4,
                               qkv_w, wqkvh, KDIM * D3 / 4,
                               o_w, woh, KDIM * DMODEL / 4);

    // 1) QKV projection
    gemm_h_kernel<__half><<<dim3(D3 / 128, MROWS / 128), 256, HSMEM_BYTES>>>(
        xh, wqkvh, qkv_b, qkvh, D3);

    // 2) causal flash attention (128-key tiles)
    attn_h_kernel<<<dim3(TSEQ / 128, NBATCH * NHEADS), 256, ATT_SMEM_BYTES>>>(
        qkvh, yh);

    // 3) output projection
    gemm_h_kernel<float><<<dim3(DMODEL / 128, MROWS / 128), 256, HSMEM_BYTES>>>(
        yh, woh, o_b, out, DMODEL);
}